// round 1
// baseline (speedup 1.0000x reference)
#include <cuda_runtime.h>
#include <math.h>

#define D_MODEL 2048
#define NH      16
#define DKDIM   128
#define BATCH   2
#define NEWLEN  2048
#define PASTLEN 2048
#define MROWS   (BATCH * NEWLEN)   // 4096

// ---------------------------------------------------------------------------
// Scratch (device globals: allocation-free, harness-legal)
// ---------------------------------------------------------------------------
__device__ float g_q[(size_t)MROWS * D_MODEL];
__device__ float g_k[(size_t)MROWS * D_MODEL];
__device__ float g_v[(size_t)MROWS * D_MODEL];
__device__ float g_o[(size_t)MROWS * D_MODEL];

// ---------------------------------------------------------------------------
// SGEMM (NT): C[m][n] = sum_k A[m][k] * B[n][k]
// A: (4096, 2048) row-major, B: (2048, 2048) row-major, C: (4096, 2048)
// Block tile 128x128, K-tile 16, 256 threads, 8x8 per-thread microtile.
// Shared staged K-major-transposed: As[k][m], Bs[k][n], pad +4.
// ---------------------------------------------------------------------------
#define BM 128
#define BN 128
#define BKK 16

__global__ __launch_bounds__(256) void sgemm_nt(const float* __restrict__ A,
                                                const float* __restrict__ B,
                                                float* __restrict__ C) {
    const int K = D_MODEL, N = D_MODEL;
    __shared__ float As[BKK][BM + 4];
    __shared__ float Bs[BKK][BN + 4];

    const int tid = threadIdx.x;
    const int tx = tid & 15;      // 0..15 -> n
    const int ty = tid >> 4;      // 0..15 -> m
    const int m0 = blockIdx.y * BM;
    const int n0 = blockIdx.x * BN;

    float acc[64];
#pragma unroll
    for (int i = 0; i < 64; i++) acc[i] = 0.f;

    for (int kt = 0; kt < K; kt += BKK) {
#pragma unroll
        for (int r = 0; r < 2; r++) {
            int lin = tid + r * 256;
            int row = lin >> 2;            // 0..127
            int kq  = (lin & 3) << 2;      // 0,4,8,12
            float4 a = *(const float4*)(A + (size_t)(m0 + row) * K + kt + kq);
            As[kq + 0][row] = a.x;
            As[kq + 1][row] = a.y;
            As[kq + 2][row] = a.z;
            As[kq + 3][row] = a.w;
            float4 bb = *(const float4*)(B + (size_t)(n0 + row) * K + kt + kq);
            Bs[kq + 0][row] = bb.x;
            Bs[kq + 1][row] = bb.y;
            Bs[kq + 2][row] = bb.z;
            Bs[kq + 3][row] = bb.w;
        }
        __syncthreads();

#pragma unroll
        for (int kk = 0; kk < BKK; kk++) {
            float4 a0 = *(const float4*)&As[kk][ty * 8];
            float4 a1 = *(const float4*)&As[kk][ty * 8 + 4];
            float4 b0 = *(const float4*)&Bs[kk][tx * 8];
            float4 b1 = *(const float4*)&Bs[kk][tx * 8 + 4];
            float av[8] = {a0.x, a0.y, a0.z, a0.w, a1.x, a1.y, a1.z, a1.w};
            float bv[8] = {b0.x, b0.y, b0.z, b0.w, b1.x, b1.y, b1.z, b1.w};
#pragma unroll
            for (int i = 0; i < 8; i++)
#pragma unroll
                for (int j = 0; j < 8; j++)
                    acc[i * 8 + j] = fmaf(av[i], bv[j], acc[i * 8 + j]);
        }
        __syncthreads();
    }

#pragma unroll
    for (int i = 0; i < 8; i++) {
        float4 c0 = make_float4(acc[i * 8 + 0], acc[i * 8 + 1], acc[i * 8 + 2], acc[i * 8 + 3]);
        float4 c1 = make_float4(acc[i * 8 + 4], acc[i * 8 + 5], acc[i * 8 + 6], acc[i * 8 + 7]);
        float* cp = C + (size_t)(m0 + ty * 8 + i) * N + n0 + tx * 8;
        *(float4*)cp = c0;
        *(float4*)(cp + 4) = c1;
    }
}

// ---------------------------------------------------------------------------
// Flash attention, fp32.
// Grid: (NEWLEN/64, NH, BATCH). 256 threads.
// Thread (qh = tid>>3, dg = tid&7) owns query rows {qh, qh+32} and d-chunks
// {dg, dg+8, dg+16, dg+24} (float4 chunks -> 2x16 output floats).
// Q, Knew, Vnew are in (b, s, e) projection layout; past K/V in (b,h,s,d).
// Shared: Qs[64][132], Kts[128][36] (K transposed), Vs[32][132], Ss[64][33].
// ---------------------------------------------------------------------------
#define QT 64
#define KTILE 32
#define SMEM_FLOATS (64 * 132 + 128 * 36 + 32 * 132 + 64 * 33)

__global__ __launch_bounds__(256, 2) void attn_kernel(
    const float* __restrict__ Qp, const float* __restrict__ Kp,
    const float* __restrict__ Vp, const float* __restrict__ pK,
    const float* __restrict__ pV, float* __restrict__ Op) {
    extern __shared__ float sm[];
    float* Qs  = sm;                   // [64][132]
    float* Kts = Qs + 64 * 132;        // [128][36]
    float* Vs  = Kts + 128 * 36;       // [32][132]
    float* Ss  = Vs + 32 * 132;        // [64][33]

    const int q0 = blockIdx.x * QT;
    const int h  = blockIdx.y;
    const int b  = blockIdx.z;
    const int tid = threadIdx.x;
    const int qh = tid >> 3;           // 0..31
    const int dg = tid & 7;            // 0..7
    const int r0 = qh, r1 = qh + 32;

    // ---- load Q tile (scaled by 1/sqrt(dk)) ----
    const float* Qb = Qp + ((size_t)(b * NEWLEN + q0)) * D_MODEL + h * DKDIM;
    for (int i = tid; i < QT * 32; i += 256) {
        int row = i >> 5;
        int c   = (i & 31) << 2;
        float4 t = *(const float4*)(Qb + (size_t)row * D_MODEL + c);
        const float s = 0.08838834764831845f;   // 1/sqrt(128)
        t.x *= s; t.y *= s; t.z *= s; t.w *= s;
        *(float4*)&Qs[row * 132 + c] = t;
    }

    float4 acc0[4], acc1[4];
#pragma unroll
    for (int i = 0; i < 4; i++) {
        acc0[i] = make_float4(0.f, 0.f, 0.f, 0.f);
        acc1[i] = make_float4(0.f, 0.f, 0.f, 0.f);
    }
    float m0r = -1e30f, m1r = -1e30f, l0 = 0.f, l1 = 0.f;

    const float* Kn  = Kp + (size_t)b * NEWLEN * D_MODEL + h * DKDIM;
    const float* Vn  = Vp + (size_t)b * NEWLEN * D_MODEL + h * DKDIM;
    const float* pKb = pK + (size_t)(b * NH + h) * PASTLEN * DKDIM;
    const float* pVb = pV + (size_t)(b * NH + h) * PASTLEN * DKDIM;

    const int nkt  = (PASTLEN + q0 + QT) / KTILE;
    const int lim0 = PASTLEN + q0 + r0;      // max visible key for row r0
    const int lim1 = lim0 + 32;              // for row r1

    for (int kt = 0; kt < nkt; kt++) {
        const int kb = kt * KTILE;

        // ---- load K (transposed) and V tiles ----
        for (int i = tid; i < KTILE * 32; i += 256) {
            int kr = i >> 5;               // 0..31
            int c  = (i & 31) << 2;        // 0,4,...,124
            int kg = kb + kr;
            const float *ks, *vsrc;
            if (kg < PASTLEN) {
                ks   = pKb + (size_t)kg * DKDIM + c;
                vsrc = pVb + (size_t)kg * DKDIM + c;
            } else {
                size_t off = (size_t)(kg - PASTLEN) * D_MODEL + c;
                ks   = Kn + off;
                vsrc = Vn + off;
            }
            float4 kv = *(const float4*)ks;
            Kts[(c + 0) * 36 + kr] = kv.x;
            Kts[(c + 1) * 36 + kr] = kv.y;
            Kts[(c + 2) * 36 + kr] = kv.z;
            Kts[(c + 3) * 36 + kr] = kv.w;
            *(float4*)&Vs[kr * 132 + c] = *(const float4*)vsrc;
        }
        __syncthreads();

        // ---- scores: rows {r0,r1} x keys {dg*4 .. dg*4+3} ----
        float s0[4] = {0.f, 0.f, 0.f, 0.f};
        float s1[4] = {0.f, 0.f, 0.f, 0.f};
#pragma unroll 8
        for (int d = 0; d < DKDIM; d++) {
            float qa = Qs[r0 * 132 + d];
            float qb2 = Qs[r1 * 132 + d];
            float4 kv = *(const float4*)&Kts[d * 36 + dg * 4];
            s0[0] = fmaf(qa, kv.x, s0[0]);
            s0[1] = fmaf(qa, kv.y, s0[1]);
            s0[2] = fmaf(qa, kv.z, s0[2]);
            s0[3] = fmaf(qa, kv.w, s0[3]);
            s1[0] = fmaf(qb2, kv.x, s1[0]);
            s1[1] = fmaf(qb2, kv.y, s1[1]);
            s1[2] = fmaf(qb2, kv.z, s1[2]);
            s1[3] = fmaf(qb2, kv.w, s1[3]);
        }

        // ---- causal mask ----
        const int kcol = kb + dg * 4;
#pragma unroll
        for (int j = 0; j < 4; j++) {
            if (kcol + j > lim0) s0[j] = -1e30f;
            if (kcol + j > lim1) s1[j] = -1e30f;
        }

        // ---- online softmax (reduce over the 8-lane octet owning each row) ----
        float mt0 = fmaxf(fmaxf(s0[0], s0[1]), fmaxf(s0[2], s0[3]));
        float mt1 = fmaxf(fmaxf(s1[0], s1[1]), fmaxf(s1[2], s1[3]));
#pragma unroll
        for (int o = 1; o < 8; o <<= 1) {
            mt0 = fmaxf(mt0, __shfl_xor_sync(0xffffffffu, mt0, o));
            mt1 = fmaxf(mt1, __shfl_xor_sync(0xffffffffu, mt1, o));
        }
        float mn0 = fmaxf(m0r, mt0), mn1 = fmaxf(m1r, mt1);
        float c0 = __expf(m0r - mn0), c1 = __expf(m1r - mn1);

        float p0[4], p1[4];
        float ps0 = 0.f, ps1 = 0.f;
#pragma unroll
        for (int j = 0; j < 4; j++) {
            p0[j] = __expf(s0[j] - mn0); ps0 += p0[j];
            p1[j] = __expf(s1[j] - mn1); ps1 += p1[j];
        }
#pragma unroll
        for (int o = 1; o < 8; o <<= 1) {
            ps0 += __shfl_xor_sync(0xffffffffu, ps0, o);
            ps1 += __shfl_xor_sync(0xffffffffu, ps1, o);
        }
        l0 = l0 * c0 + ps0;
        l1 = l1 * c1 + ps1;
        m0r = mn0;
        m1r = mn1;

        // ---- share P within the octet ----
#pragma unroll
        for (int j = 0; j < 4; j++) {
            Ss[r0 * 33 + dg * 4 + j] = p0[j];
            Ss[r1 * 33 + dg * 4 + j] = p1[j];
        }
        __syncwarp();

        // ---- rescale accumulators ----
#pragma unroll
        for (int i = 0; i < 4; i++) {
            acc0[i].x *= c0; acc0[i].y *= c0; acc0[i].z *= c0; acc0[i].w *= c0;
            acc1[i].x *= c1; acc1[i].y *= c1; acc1[i].z *= c1; acc1[i].w *= c1;
        }

        // ---- O += P @ V ----
#pragma unroll 4
        for (int kj = 0; kj < KTILE; kj++) {
            float pa = Ss[r0 * 33 + kj];
            float pb = Ss[r1 * 33 + kj];
#pragma unroll
            for (int i = 0; i < 4; i++) {
                float4 vv = *(const float4*)&Vs[kj * 132 + (dg + 8 * i) * 4];
                acc0[i].x = fmaf(pa, vv.x, acc0[i].x);
                acc0[i].y = fmaf(pa, vv.y, acc0[i].y);
                acc0[i].z = fmaf(pa, vv.z, acc0[i].z);
                acc0[i].w = fmaf(pa, vv.w, acc0[i].w);
                acc1[i].x = fmaf(pb, vv.x, acc1[i].x);
                acc1[i].y = fmaf(pb, vv.y, acc1[i].y);
                acc1[i].z = fmaf(pb, vv.z, acc1[i].z);
                acc1[i].w = fmaf(pb, vv.w, acc1[i].w);
            }
        }
        __syncthreads();
    }

    // ---- epilogue ----
    float i0 = 1.f / l0, i1 = 1.f / l1;
    float* Ob = Op + ((size_t)(b * NEWLEN + q0)) * D_MODEL + h * DKDIM;
#pragma unroll
    for (int i = 0; i < 4; i++) {
        int c = (dg + 8 * i) * 4;
        float4 o0 = make_float4(acc0[i].x * i0, acc0[i].y * i0, acc0[i].z * i0, acc0[i].w * i0);
        float4 o1 = make_float4(acc1[i].x * i1, acc1[i].y * i1, acc1[i].z * i1, acc1[i].w * i1);
        *(float4*)(Ob + (size_t)r0 * D_MODEL + c) = o0;
        *(float4*)(Ob + (size_t)r1 * D_MODEL + c) = o1;
    }
}

// ---------------------------------------------------------------------------
// Launch
// inputs: x, past_key, past_value, Wq, Wk, Wv, Wo   (all fp32)
// ---------------------------------------------------------------------------
extern "C" void kernel_launch(void* const* d_in, const int* in_sizes, int n_in,
                              void* d_out, int out_size) {
    const float* x     = (const float*)d_in[0];
    const float* pastK = (const float*)d_in[1];
    const float* pastV = (const float*)d_in[2];
    const float* Wq    = (const float*)d_in[3];
    const float* Wk    = (const float*)d_in[4];
    const float* Wv    = (const float*)d_in[5];
    const float* Wo    = (const float*)d_in[6];
    float* out = (float*)d_out;

    float *q, *k, *v, *o;
    cudaGetSymbolAddress((void**)&q, g_q);
    cudaGetSymbolAddress((void**)&k, g_k);
    cudaGetSymbolAddress((void**)&v, g_v);
    cudaGetSymbolAddress((void**)&o, g_o);

    dim3 gemm_grid(D_MODEL / BN, MROWS / BM);   // (16, 32)
    sgemm_nt<<<gemm_grid, 256>>>(x, Wq, q);
    sgemm_nt<<<gemm_grid, 256>>>(x, Wk, k);
    sgemm_nt<<<gemm_grid, 256>>>(x, Wv, v);

    size_t smem = (size_t)SMEM_FLOATS * sizeof(float);   // ~77.6 KB
    cudaFuncSetAttribute(attn_kernel, cudaFuncAttributeMaxDynamicSharedMemorySize,
                         (int)smem);
    attn_kernel<<<dim3(NEWLEN / QT, NH, BATCH), 256, smem>>>(q, k, v, pastK, pastV, o);

    sgemm_nt<<<gemm_grid, 256>>>(o, Wo, out);
}

// round 3
// speedup vs baseline: 2.6239x; 2.6239x over previous
#include <cuda_runtime.h>
#include <math.h>

#define D_MODEL 2048
#define NH      16
#define DKDIM   128
#define BATCH   2
#define NEWLEN  2048
#define PASTLEN 2048
#define MROWS   (BATCH * NEWLEN)   // 4096

// ---------------------------------------------------------------------------
// Scratch (device globals: allocation-free, harness-legal)
// ---------------------------------------------------------------------------
__device__ float g_q[(size_t)MROWS * D_MODEL];
__device__ float g_k[(size_t)MROWS * D_MODEL];
__device__ float g_v[(size_t)MROWS * D_MODEL];
__device__ float g_o[(size_t)MROWS * D_MODEL];

// ---------------------------------------------------------------------------
// TF32 helpers
// ---------------------------------------------------------------------------
__device__ __forceinline__ unsigned f2tf(float x) {
    unsigned u;
    asm("cvt.rna.tf32.f32 %0, %1;" : "=r"(u) : "f"(x));
    return u;
}

__device__ __forceinline__ float fexp2(float x) {
    float y;
    asm("ex2.approx.ftz.f32 %0, %1;" : "=f"(y) : "f"(x));
    return y;
}

// D += A*B  (m16n8k8, tf32 inputs, fp32 accum)
__device__ __forceinline__ void mma8(float* d, const unsigned* a, const unsigned* b) {
    asm volatile(
        "mma.sync.aligned.m16n8k8.row.col.f32.tf32.tf32.f32 "
        "{%0,%1,%2,%3}, {%4,%5,%6,%7}, {%8,%9}, {%0,%1,%2,%3};\n"
        : "+f"(d[0]), "+f"(d[1]), "+f"(d[2]), "+f"(d[3])
        : "r"(a[0]), "r"(a[1]), "r"(a[2]), "r"(a[3]), "r"(b[0]), "r"(b[1]));
}

// Fragment-position helpers (m16n8k8):
//  A atom (16x8):  lane = (r&7)*4 + (c&3), reg = (r>>3) + 2*(c>>2)
//  B atom (8k x 8n): lane = n*4 + (k&3),   reg = k>>2
//  C atom (16x8):  [0]=(gid,2t) [1]=(gid,2t+1) [2]=(gid+8,2t) [3]=(gid+8,2t+1)

// ---------------------------------------------------------------------------
// TF32 GEMM (NT): C[m][n] = sum_k A[m][k] * B[n][k]
// A (4096,2048), B (2048,2048), C (4096,2048) all row-major fp32.
// Block 128x128x32, 256 threads, warps 2(m) x 4(n), warp tile 64x32.
// ---------------------------------------------------------------------------
__global__ __launch_bounds__(256, 2) void gemm_tf32(const float* __restrict__ A,
                                                    const float* __restrict__ B,
                                                    float* __restrict__ C) {
    const int K = D_MODEL, N = D_MODEL;
    __shared__ unsigned AF[4 * 8 * 128];    // [ka][matom][lane*4+reg]
    __shared__ unsigned BF[4 * 16 * 64];    // [ka][natom][lane*2+reg]

    const int tid  = threadIdx.x;
    const int lane = tid & 31;
    const int warp = tid >> 5;
    const int wm   = warp >> 2;       // 0..1
    const int wn   = warp & 3;        // 0..3
    const int gid  = lane >> 2;
    const int tig  = lane & 3;
    const int m0 = blockIdx.y * 128;
    const int n0 = blockIdx.x * 128;

    float acc[4][4][4];
#pragma unroll
    for (int i = 0; i < 4; i++)
#pragma unroll
        for (int j = 0; j < 4; j++)
#pragma unroll
            for (int r = 0; r < 4; r++) acc[i][j][r] = 0.f;

    for (int kt = 0; kt < K; kt += 32) {
        // ---- stage A,B tiles into fragment layout (tf32-converted) ----
#pragma unroll
        for (int i = 0; i < 4; i++) {
            int p   = tid + i * 256;
            int row = p >> 3;             // 0..127
            int kq  = (p & 7) << 2;       // 0..28
            float4 a = *(const float4*)(A + (size_t)(m0 + row) * K + kt + kq);
            float4 b = *(const float4*)(B + (size_t)(n0 + row) * K + kt + kq);
            float av[4] = {a.x, a.y, a.z, a.w};
            float bv[4] = {b.x, b.y, b.z, b.w};
            int ma = row >> 4, ra = row & 15;
            int na = row >> 3, nn = row & 7;
#pragma unroll
            for (int j = 0; j < 4; j++) {
                int k = kq + j, ka = k >> 3, c = k & 7;
                AF[(ka * 8 + ma) * 128 + ((ra & 7) * 4 + (c & 3)) * 4 + (ra >> 3) + 2 * (c >> 2)] = f2tf(av[j]);
                BF[(ka * 16 + na) * 64 + (nn * 4 + (c & 3)) * 2 + (c >> 2)] = f2tf(bv[j]);
            }
        }
        __syncthreads();

        // ---- compute ----
#pragma unroll
        for (int ka = 0; ka < 4; ka++) {
            unsigned af[4][4], bf[4][2];
#pragma unroll
            for (int i = 0; i < 4; i++)
                *(uint4*)af[i] = *(const uint4*)&AF[(ka * 8 + wm * 4 + i) * 128 + lane * 4];
#pragma unroll
            for (int j = 0; j < 4; j++)
                *(uint2*)bf[j] = *(const uint2*)&BF[(ka * 16 + wn * 4 + j) * 64 + lane * 2];
#pragma unroll
            for (int i = 0; i < 4; i++)
#pragma unroll
                for (int j = 0; j < 4; j++) mma8(acc[i][j], af[i], bf[j]);
        }
        __syncthreads();
    }

    // ---- epilogue ----
#pragma unroll
    for (int i = 0; i < 4; i++) {
        int r0 = m0 + wm * 64 + i * 16 + gid;
#pragma unroll
        for (int j = 0; j < 4; j++) {
            int cc = n0 + wn * 32 + j * 8 + tig * 2;
            *(float2*)&C[(size_t)r0 * N + cc]       = make_float2(acc[i][j][0], acc[i][j][1]);
            *(float2*)&C[(size_t)(r0 + 8) * N + cc] = make_float2(acc[i][j][2], acc[i][j][3]);
        }
    }
}

// ---------------------------------------------------------------------------
// Flash attention, TF32 tensor cores.
// Grid (NEWLEN/128, NH, BATCH), 256 threads (8 warps).
// Warp w owns Q rows [q0 + 16w, q0 + 16w + 16). Q frags held in registers.
// Per key-tile (64 keys): S = Q K^T via mma, online softmax (log2 domain),
// P restaged through shared as A-frags, O += P V via mma.
// ---------------------------------------------------------------------------
#define QT 128
#define KT 64
// smem (unsigned words): KF 16*8*64=8192, VF 8*16*64=8192, PF 8*8*128=8192
#define ATTN_SMEM_WORDS (8192 * 3)

__global__ __launch_bounds__(256, 1) void attn_tf32(
    const float* __restrict__ Qp, const float* __restrict__ Kp,
    const float* __restrict__ Vp, const float* __restrict__ pK,
    const float* __restrict__ pV, float* __restrict__ Op) {
    extern __shared__ unsigned sm_u[];
    unsigned* KF = sm_u;            // [ka(16)][na(8)][64]
    unsigned* VF = sm_u + 8192;     // [ka(8)][na(16)][64]
    unsigned* PF = sm_u + 16384;    // [warp(8)][ka(8)][128]

    const int tid  = threadIdx.x;
    const int lane = tid & 31;
    const int warp = tid >> 5;
    const int gid  = lane >> 2;
    const int tig  = lane & 3;
    const int q0 = blockIdx.x * QT;
    const int h  = blockIdx.y;
    const int b  = blockIdx.z;

    // ---- Q fragments in registers (scaled by 1/sqrt(dk) * log2(e)) ----
    const float qscale = 0.08838834764831845f * 1.4426950408889634f;
    const float* Qb = Qp + ((size_t)(b * NEWLEN + q0 + warp * 16)) * D_MODEL + h * DKDIM;
    unsigned qf[16][4];
#pragma unroll
    for (int ka = 0; ka < 16; ka++) {
        int c0 = ka * 8 + tig;
        qf[ka][0] = f2tf(Qb[(size_t)gid * D_MODEL + c0] * qscale);
        qf[ka][1] = f2tf(Qb[(size_t)(gid + 8) * D_MODEL + c0] * qscale);
        qf[ka][2] = f2tf(Qb[(size_t)gid * D_MODEL + c0 + 4] * qscale);
        qf[ka][3] = f2tf(Qb[(size_t)(gid + 8) * D_MODEL + c0 + 4] * qscale);
    }

    float o[16][4];
#pragma unroll
    for (int na = 0; na < 16; na++)
#pragma unroll
        for (int r = 0; r < 4; r++) o[na][r] = 0.f;
    float m0 = -1e30f, m1 = -1e30f, l0 = 0.f, l1 = 0.f;

    const float* Kn  = Kp + (size_t)b * NEWLEN * D_MODEL + h * DKDIM;
    const float* Vn  = Vp + (size_t)b * NEWLEN * D_MODEL + h * DKDIM;
    const float* pKb = pK + (size_t)(b * NH + h) * PASTLEN * DKDIM;
    const float* pVb = pV + (size_t)(b * NH + h) * PASTLEN * DKDIM;

    const int nkt = (PASTLEN + q0 + QT) / KT;
    const int qa0 = PASTLEN + q0 + warp * 16 + gid;   // abs pos of row0 (row1 = qa0+8)

    for (int kt = 0; kt < nkt; kt++) {
        const int kb = kt * KT;

        // ---- stage K (S-frags) and V (PV-frags), tf32-converted ----
#pragma unroll
        for (int i = 0; i < 8; i++) {
            int p  = tid + i * 256;
            int kr = p & 63;               // key row in tile
            int cq = (p >> 6) << 2;        // d column (0..124)
            int kg = kb + kr;
            const float *ks, *vs;
            if (kg < PASTLEN) {
                ks = pKb + (size_t)kg * DKDIM + cq;
                vs = pVb + (size_t)kg * DKDIM + cq;
            } else {
                size_t off = (size_t)(kg - PASTLEN) * D_MODEL + cq;
                ks = Kn + off;
                vs = Vn + off;
            }
            float4 kv = *(const float4*)ks;
            float4 vv = *(const float4*)vs;
            float ke[4] = {kv.x, kv.y, kv.z, kv.w};
            float ve[4] = {vv.x, vv.y, vv.z, vv.w};
#pragma unroll
            for (int j = 0; j < 4; j++) {
                int c = cq + j;
                // K: katom over d, natom over key. (k=c&7, n=kr&7)
                KF[((c >> 3) * 8 + (kr >> 3)) * 64 + ((kr & 7) * 4 + (c & 3)) * 2 + ((c & 7) >> 2)] = f2tf(ke[j]);
                // V: katom over key, natom over d. (k=kr&7, n=c&7)
                VF[((kr >> 3) * 16 + (c >> 3)) * 64 + ((c & 7) * 4 + (kr & 3)) * 2 + ((kr & 7) >> 2)] = f2tf(ve[j]);
            }
        }
        __syncthreads();

        // ---- S = Q K^T ----
        float s[8][4];
#pragma unroll
        for (int na = 0; na < 8; na++)
#pragma unroll
            for (int r = 0; r < 4; r++) s[na][r] = 0.f;
#pragma unroll
        for (int ka = 0; ka < 16; ka++) {
#pragma unroll
            for (int na = 0; na < 8; na++) {
                unsigned bf[2];
                *(uint2*)bf = *(const uint2*)&KF[(ka * 8 + na) * 64 + lane * 2];
                mma8(s[na], qf[ka], bf);
            }
        }

        // ---- causal mask ----
        if (kb + KT - 1 > qa0) {
#pragma unroll
            for (int na = 0; na < 8; na++) {
                int key = kb + na * 8 + tig * 2;
                if (key     > qa0)     s[na][0] = -1e30f;
                if (key + 1 > qa0)     s[na][1] = -1e30f;
                if (key     > qa0 + 8) s[na][2] = -1e30f;
                if (key + 1 > qa0 + 8) s[na][3] = -1e30f;
            }
        }

        // ---- online softmax (log2 domain), rows reduced over 4-lane tig group ----
        float mx0 = -1e30f, mx1 = -1e30f;
#pragma unroll
        for (int na = 0; na < 8; na++) {
            mx0 = fmaxf(mx0, fmaxf(s[na][0], s[na][1]));
            mx1 = fmaxf(mx1, fmaxf(s[na][2], s[na][3]));
        }
        mx0 = fmaxf(mx0, __shfl_xor_sync(0xffffffffu, mx0, 1));
        mx0 = fmaxf(mx0, __shfl_xor_sync(0xffffffffu, mx0, 2));
        mx1 = fmaxf(mx1, __shfl_xor_sync(0xffffffffu, mx1, 1));
        mx1 = fmaxf(mx1, __shfl_xor_sync(0xffffffffu, mx1, 2));
        float nm0 = fmaxf(m0, mx0), nm1 = fmaxf(m1, mx1);
        float c0 = fexp2(m0 - nm0), c1 = fexp2(m1 - nm1);
        float sum0 = 0.f, sum1 = 0.f;
#pragma unroll
        for (int na = 0; na < 8; na++) {
            s[na][0] = fexp2(s[na][0] - nm0); sum0 += s[na][0];
            s[na][1] = fexp2(s[na][1] - nm0); sum0 += s[na][1];
            s[na][2] = fexp2(s[na][2] - nm1); sum1 += s[na][2];
            s[na][3] = fexp2(s[na][3] - nm1); sum1 += s[na][3];
        }
        sum0 += __shfl_xor_sync(0xffffffffu, sum0, 1);
        sum0 += __shfl_xor_sync(0xffffffffu, sum0, 2);
        sum1 += __shfl_xor_sync(0xffffffffu, sum1, 1);
        sum1 += __shfl_xor_sync(0xffffffffu, sum1, 2);
        l0 = l0 * c0 + sum0;
        l1 = l1 * c1 + sum1;
        m0 = nm0; m1 = nm1;

        // ---- rescale O ----
#pragma unroll
        for (int na = 0; na < 16; na++) {
            o[na][0] *= c0; o[na][1] *= c0;
            o[na][2] *= c1; o[na][3] *= c1;
        }

        // ---- restage P (C-frag -> A-frag layout), per-warp region ----
        unsigned* pfw = PF + warp * 1024;
        {
            int la  = gid * 4;
            int c0i = (tig * 2) & 3,     c0h = (tig * 2) >> 2;
            int c1i = (tig * 2 + 1) & 3, c1h = (tig * 2 + 1) >> 2;
#pragma unroll
            for (int na = 0; na < 8; na++) {
                pfw[na * 128 + (la + c0i) * 4 + 0 + 2 * c0h] = f2tf(s[na][0]);
                pfw[na * 128 + (la + c1i) * 4 + 0 + 2 * c1h] = f2tf(s[na][1]);
                pfw[na * 128 + (la + c0i) * 4 + 1 + 2 * c0h] = f2tf(s[na][2]);
                pfw[na * 128 + (la + c1i) * 4 + 1 + 2 * c1h] = f2tf(s[na][3]);
            }
        }
        __syncwarp();

        // ---- O += P V ----
#pragma unroll
        for (int ka = 0; ka < 8; ka++) {
            unsigned pa[4];
            *(uint4*)pa = *(const uint4*)&pfw[ka * 128 + lane * 4];
#pragma unroll
            for (int na = 0; na < 16; na++) {
                unsigned bf[2];
                *(uint2*)bf = *(const uint2*)&VF[(ka * 16 + na) * 64 + lane * 2];
                mma8(o[na], pa, bf);
            }
        }
        __syncthreads();
    }

    // ---- epilogue: O / l ----
    float r0i = 1.f / l0, r1i = 1.f / l1;
    float* Ob = Op + ((size_t)(b * NEWLEN + q0 + warp * 16)) * D_MODEL + h * DKDIM;
#pragma unroll
    for (int na = 0; na < 16; na++) {
        int c = na * 8 + tig * 2;
        *(float2*)&Ob[(size_t)gid * D_MODEL + c]       = make_float2(o[na][0] * r0i, o[na][1] * r0i);
        *(float2*)&Ob[(size_t)(gid + 8) * D_MODEL + c] = make_float2(o[na][2] * r1i, o[na][3] * r1i);
    }
}

// ---------------------------------------------------------------------------
// Launch
// ---------------------------------------------------------------------------
extern "C" void kernel_launch(void* const* d_in, const int* in_sizes, int n_in,
                              void* d_out, int out_size) {
    const float* x     = (const float*)d_in[0];
    const float* pastK = (const float*)d_in[1];
    const float* pastV = (const float*)d_in[2];
    const float* Wq    = (const float*)d_in[3];
    const float* Wk    = (const float*)d_in[4];
    const float* Wv    = (const float*)d_in[5];
    const float* Wo    = (const float*)d_in[6];
    float* out = (float*)d_out;

    float *q, *k, *v, *o;
    cudaGetSymbolAddress((void**)&q, g_q);
    cudaGetSymbolAddress((void**)&k, g_k);
    cudaGetSymbolAddress((void**)&v, g_v);
    cudaGetSymbolAddress((void**)&o, g_o);

    dim3 gemm_grid(D_MODEL / 128, MROWS / 128);   // (16, 32)
    gemm_tf32<<<gemm_grid, 256>>>(x, Wq, q);
    gemm_tf32<<<gemm_grid, 256>>>(x, Wk, k);
    gemm_tf32<<<gemm_grid, 256>>>(x, Wv, v);

    size_t smem = (size_t)ATTN_SMEM_WORDS * sizeof(unsigned);   // 96 KB
    cudaFuncSetAttribute(attn_tf32, cudaFuncAttributeMaxDynamicSharedMemorySize, (int)smem);
    attn_tf32<<<dim3(NEWLEN / QT, NH, BATCH), 256, smem>>>(q, k, v, pastK, pastV, o);

    gemm_tf32<<<gemm_grid, 256>>>(o, Wo, out);
}

// round 5
// speedup vs baseline: 2.6988x; 1.0285x over previous
#include <cuda_runtime.h>
#include <math.h>
#include <stdint.h>

#define D_MODEL 2048
#define NH      16
#define DKDIM   128
#define BATCH   2
#define NEWLEN  2048
#define PASTLEN 2048
#define MROWS   (BATCH * NEWLEN)   // 4096

// ---------------------------------------------------------------------------
// Scratch (device globals: allocation-free, harness-legal)
// ---------------------------------------------------------------------------
__device__ float g_q[(size_t)MROWS * D_MODEL];
__device__ float g_k[(size_t)MROWS * D_MODEL];
__device__ float g_v[(size_t)MROWS * D_MODEL];
__device__ float g_o[(size_t)MROWS * D_MODEL];

// ---------------------------------------------------------------------------
// Helpers
// ---------------------------------------------------------------------------
__device__ __forceinline__ unsigned f2tf(float x) {
    unsigned u;
    asm("cvt.rna.tf32.f32 %0, %1;" : "=r"(u) : "f"(x));
    return u;
}

__device__ __forceinline__ float fexp2(float x) {
    float y;
    asm("ex2.approx.ftz.f32 %0, %1;" : "=f"(y) : "f"(x));
    return y;
}

// D += A*B  (m16n8k8, tf32 inputs, fp32 accum)
__device__ __forceinline__ void mma8(float* d, const unsigned* a, const unsigned* b) {
    asm volatile(
        "mma.sync.aligned.m16n8k8.row.col.f32.tf32.tf32.f32 "
        "{%0,%1,%2,%3}, {%4,%5,%6,%7}, {%8,%9}, {%0,%1,%2,%3};\n"
        : "+f"(d[0]), "+f"(d[1]), "+f"(d[2]), "+f"(d[3])
        : "r"(a[0]), "r"(a[1]), "r"(a[2]), "r"(a[3]), "r"(b[0]), "r"(b[1]));
}

// Fragment maps (m16n8k8):
//  A atom (16x8):  lane = (r&7)*4 + (c&3), reg = (r>>3) + 2*(c>>2)
//  B atom (8k x 8n): lane = n*4 + (k&3),   reg = k>>2
//  C atom (16x8):  [0]=(gid,2t) [1]=(gid,2t+1) [2]=(gid+8,2t) [3]=(gid+8,2t+1)

// ---------------------------------------------------------------------------
// TF32 GEMM body (NT): C[m][n] = sum_k A[m][k]*B[n][k]
// Block 128x128x32, 256 threads, warps 2(m) x 4(n), warp tile 64x32.
// Double-buffered fragment smem, register-prefetch pipeline, 1 sync/iter.
// ---------------------------------------------------------------------------
#define GEMM_BUF_WORDS 8192                 // AF 4096 + BF 4096 per buffer
#define GEMM_SMEM_BYTES (2 * GEMM_BUF_WORDS * 4)   // 64 KB

__device__ __forceinline__ void gemm_body(const float* __restrict__ A,
                                          const float* __restrict__ B,
                                          float* __restrict__ C,
                                          unsigned* sg, int m0, int n0) {
    const int K = D_MODEL, N = D_MODEL;
    const int tid  = threadIdx.x;
    const int lane = tid & 31;
    const int warp = tid >> 5;
    const int wm   = warp >> 2;
    const int wn   = warp & 3;
    const int gid  = lane >> 2;
    const int tig  = lane & 3;

    // staging geometry: thread -> row srow+32*ch, cols skq..skq+3
    const int srow = tid >> 3;         // 0..31
    const int skq  = (tid & 7) << 2;   // 0..28

    auto ldch = [&](int ch, int ktn, float4& a4, float4& b4) {
        int row = srow + 32 * ch;
        a4 = *(const float4*)(A + (size_t)(m0 + row) * K + ktn * 32 + skq);
        b4 = *(const float4*)(B + (size_t)(n0 + row) * K + ktn * 32 + skq);
    };
    auto stch = [&](int ch, unsigned* AFn, unsigned* BFn, const float4& a4, const float4& b4) {
        int row = srow + 32 * ch;
        int ma = row >> 4, ra = row & 15;
        int na = row >> 3, nn = row & 7;
        float av[4] = {a4.x, a4.y, a4.z, a4.w};
        float bv[4] = {b4.x, b4.y, b4.z, b4.w};
#pragma unroll
        for (int j = 0; j < 4; j++) {
            int k = skq + j, ka = k >> 3, c = k & 7;
            AFn[(ka * 8 + ma) * 128 + ((ra & 7) * 4 + (c & 3)) * 4 + (ra >> 3) + 2 * (c >> 2)] = f2tf(av[j]);
            BFn[(ka * 16 + na) * 64 + (nn * 4 + (c & 3)) * 2 + (c >> 2)] = f2tf(bv[j]);
        }
    };

    float acc[4][4][4];
#pragma unroll
    for (int i = 0; i < 4; i++)
#pragma unroll
        for (int j = 0; j < 4; j++)
#pragma unroll
            for (int r = 0; r < 4; r++) acc[i][j][r] = 0.f;

    // prologue: stage k-tile 0 into buffer 0
#pragma unroll
    for (int ch = 0; ch < 4; ch++) {
        float4 a4, b4;
        ldch(ch, 0, a4, b4);
        stch(ch, sg, sg + 4096, a4, b4);
    }
    __syncthreads();

    const int NKT = K / 32;
    float4 pa[2], pb[2];
    for (int kt = 0; kt < NKT; kt++) {
        unsigned* AFc = sg + (kt & 1) * GEMM_BUF_WORDS;
        unsigned* BFc = AFc + 4096;
        unsigned* AFn = sg + ((kt & 1) ^ 1) * GEMM_BUF_WORDS;
        unsigned* BFn = AFn + 4096;
        const bool more = (kt + 1 < NKT);

#pragma unroll
        for (int ka = 0; ka < 4; ka++) {
            if (more && ka > 0) stch(ka - 1, AFn, BFn, pa[(ka - 1) & 1], pb[(ka - 1) & 1]);
            if (more) ldch(ka, kt + 1, pa[ka & 1], pb[ka & 1]);

            unsigned af[4][4], bf[4][2];
#pragma unroll
            for (int i = 0; i < 4; i++)
                *(uint4*)af[i] = *(const uint4*)&AFc[(ka * 8 + wm * 4 + i) * 128 + lane * 4];
#pragma unroll
            for (int j = 0; j < 4; j++)
                *(uint2*)bf[j] = *(const uint2*)&BFc[(ka * 16 + wn * 4 + j) * 64 + lane * 2];
#pragma unroll
            for (int i = 0; i < 4; i++)
#pragma unroll
                for (int j = 0; j < 4; j++) mma8(acc[i][j], af[i], bf[j]);
        }
        if (more) stch(3, AFn, BFn, pa[1], pb[1]);
        __syncthreads();
    }

#pragma unroll
    for (int i = 0; i < 4; i++) {
        int r0 = m0 + wm * 64 + i * 16 + gid;
#pragma unroll
        for (int j = 0; j < 4; j++) {
            int cc = n0 + wn * 32 + j * 8 + tig * 2;
            *(float2*)&C[(size_t)r0 * N + cc]       = make_float2(acc[i][j][0], acc[i][j][1]);
            *(float2*)&C[(size_t)(r0 + 8) * N + cc] = make_float2(acc[i][j][2], acc[i][j][3]);
        }
    }
}

// Fused Q/K/V projection: blockIdx.z selects weight/output.
__global__ __launch_bounds__(256, 2) void gemm_qkv(const float* __restrict__ x,
                                                   const float* __restrict__ Wq,
                                                   const float* __restrict__ Wk,
                                                   const float* __restrict__ Wv,
                                                   float* __restrict__ q,
                                                   float* __restrict__ k,
                                                   float* __restrict__ v) {
    extern __shared__ unsigned sg[];
    const float* B = (blockIdx.z == 0) ? Wq : (blockIdx.z == 1) ? Wk : Wv;
    float* C = (blockIdx.z == 0) ? q : (blockIdx.z == 1) ? k : v;
    gemm_body(x, B, C, sg, blockIdx.y * 128, blockIdx.x * 128);
}

__global__ __launch_bounds__(256, 2) void gemm_one(const float* __restrict__ A,
                                                   const float* __restrict__ B,
                                                   float* __restrict__ C) {
    extern __shared__ unsigned sg[];
    gemm_body(A, B, C, sg, blockIdx.y * 128, blockIdx.x * 128);
}

// ---------------------------------------------------------------------------
// Flash attention, TF32 warp tensor cores, double-buffered K/V staging.
// Grid (NEWLEN/128, NH, BATCH), 256 threads (8 warps), warp owns 16 q rows.
// smem layout (words): [buf0: KF 8192 | VF 8192][buf1: KF | VF][PF 8192]
// ---------------------------------------------------------------------------
#define QT 128
#define KT 64
#define ATTN_BUF_WORDS 16384
#define ATTN_SMEM_BYTES ((2 * ATTN_BUF_WORDS + 8192) * 4)   // 160 KB

__global__ __launch_bounds__(256, 1) void attn_tf32(
    const float* __restrict__ Qp, const float* __restrict__ Kp,
    const float* __restrict__ Vp, const float* __restrict__ pK,
    const float* __restrict__ pV, float* __restrict__ Op) {
    extern __shared__ unsigned sm_u[];
    unsigned* PF = sm_u + 2 * ATTN_BUF_WORDS;   // [warp(8)][ka(8)][128]

    const int tid  = threadIdx.x;
    const int lane = tid & 31;
    const int warp = tid >> 5;
    const int gid  = lane >> 2;
    const int tig  = lane & 3;
    const int q0 = (gridDim.x - 1 - blockIdx.x) * QT;   // largest-first ordering
    const int h  = blockIdx.y;
    const int b  = blockIdx.z;

    const float* Kn  = Kp + (size_t)b * NEWLEN * D_MODEL + h * DKDIM;
    const float* Vn  = Vp + (size_t)b * NEWLEN * D_MODEL + h * DKDIM;
    const float* pKb = pK + (size_t)(b * NH + h) * PASTLEN * DKDIM;
    const float* pVb = pV + (size_t)(b * NH + h) * PASTLEN * DKDIM;

    // ---- Q fragments in registers (scaled by 1/sqrt(dk) * log2(e)) ----
    const float qscale = 0.08838834764831845f * 1.4426950408889634f;
    const float* Qb = Qp + ((size_t)(b * NEWLEN + q0 + warp * 16)) * D_MODEL + h * DKDIM;
    unsigned qf[16][4];
#pragma unroll
    for (int ka = 0; ka < 16; ka++) {
        int c0 = ka * 8 + tig;
        qf[ka][0] = f2tf(Qb[(size_t)gid * D_MODEL + c0] * qscale);
        qf[ka][1] = f2tf(Qb[(size_t)(gid + 8) * D_MODEL + c0] * qscale);
        qf[ka][2] = f2tf(Qb[(size_t)gid * D_MODEL + c0 + 4] * qscale);
        qf[ka][3] = f2tf(Qb[(size_t)(gid + 8) * D_MODEL + c0 + 4] * qscale);
    }

    float o[16][4];
#pragma unroll
    for (int na = 0; na < 16; na++)
#pragma unroll
        for (int r = 0; r < 4; r++) o[na][r] = 0.f;
    float m0 = -1e30f, m1 = -1e30f, l0 = 0.f, l1 = 0.f;

    // staging geometry: thread -> key row kr (fixed), cols vary per chunk
    const int kr = tid & 63;
    int kb2 = 0;                      // base key of tile being prefetched
    unsigned* KFn = sm_u;             // prefetch target buffers
    unsigned* VFn = sm_u + 8192;

    auto ld_chunk = [&](int ch, float4& kk, float4& vv) {
        int cq = (((tid >> 6) + 4 * ch) << 2);
        int kg = kb2 + kr;
        const float *ks, *vs;
        if (kg < PASTLEN) {
            ks = pKb + (size_t)kg * DKDIM + cq;
            vs = pVb + (size_t)kg * DKDIM + cq;
        } else {
            size_t off = (size_t)(kg - PASTLEN) * D_MODEL + cq;
            ks = Kn + off;
            vs = Vn + off;
        }
        kk = *(const float4*)ks;
        vv = *(const float4*)vs;
    };
    auto st_chunk = [&](int ch, const float4& kk, const float4& vv) {
        int cq = (((tid >> 6) + 4 * ch) << 2);
        float ke[4] = {kk.x, kk.y, kk.z, kk.w};
        float ve[4] = {vv.x, vv.y, vv.z, vv.w};
#pragma unroll
        for (int j = 0; j < 4; j++) {
            int c = cq + j;
            KFn[((c >> 3) * 8 + (kr >> 3)) * 64 + ((kr & 7) * 4 + (c & 3)) * 2 + ((c & 7) >> 2)] = f2tf(ke[j]);
            VFn[((kr >> 3) * 16 + (c >> 3)) * 64 + ((c & 7) * 4 + (kr & 3)) * 2 + ((kr & 7) >> 2)] = f2tf(ve[j]);
        }
    };

    // ---- prologue: stage tile 0 into buffer 0 ----
#pragma unroll
    for (int ch = 0; ch < 8; ch++) {
        float4 kk, vv;
        ld_chunk(ch, kk, vv);
        st_chunk(ch, kk, vv);
    }
    __syncthreads();

    const int nkt = (PASTLEN + q0 + QT) / KT;
    const int qa0 = PASTLEN + q0 + warp * 16 + gid;   // abs pos of row0 (row1 = +8)

    for (int kt = 0; kt < nkt; kt++) {
        const int kb = kt * KT;
        const int cur = kt & 1;
        unsigned* KFc = sm_u + cur * ATTN_BUF_WORDS;
        unsigned* VFc = KFc + 8192;
        KFn = sm_u + (cur ^ 1) * ATTN_BUF_WORDS;
        VFn = KFn + 8192;
        kb2 = kb + KT;
        const bool more = (kt + 1 < nkt);

        // ---- S = Q K^T with interleaved prefetch of next tile ----
        float s[8][4];
#pragma unroll
        for (int na = 0; na < 8; na++)
#pragma unroll
            for (int r = 0; r < 4; r++) s[na][r] = 0.f;

        float4 kpre, vpre;
#pragma unroll
        for (int ka = 0; ka < 16; ka++) {
            if (more && !(ka & 1)) ld_chunk(ka >> 1, kpre, vpre);
#pragma unroll
            for (int na = 0; na < 8; na++) {
                unsigned bf[2];
                *(uint2*)bf = *(const uint2*)&KFc[(ka * 8 + na) * 64 + lane * 2];
                mma8(s[na], qf[ka], bf);
            }
            if (more && (ka & 1)) st_chunk(ka >> 1, kpre, vpre);
        }

        // ---- causal mask ----
        if (kb + KT - 1 > qa0) {
#pragma unroll
            for (int na = 0; na < 8; na++) {
                int key = kb + na * 8 + tig * 2;
                if (key     > qa0)     s[na][0] = -1e30f;
                if (key + 1 > qa0)     s[na][1] = -1e30f;
                if (key     > qa0 + 8) s[na][2] = -1e30f;
                if (key + 1 > qa0 + 8) s[na][3] = -1e30f;
            }
        }

        // ---- online softmax (log2 domain), 4-lane row groups ----
        float mx0 = -1e30f, mx1 = -1e30f;
#pragma unroll
        for (int na = 0; na < 8; na++) {
            mx0 = fmaxf(mx0, fmaxf(s[na][0], s[na][1]));
            mx1 = fmaxf(mx1, fmaxf(s[na][2], s[na][3]));
        }
        mx0 = fmaxf(mx0, __shfl_xor_sync(0xffffffffu, mx0, 1));
        mx0 = fmaxf(mx0, __shfl_xor_sync(0xffffffffu, mx0, 2));
        mx1 = fmaxf(mx1, __shfl_xor_sync(0xffffffffu, mx1, 1));
        mx1 = fmaxf(mx1, __shfl_xor_sync(0xffffffffu, mx1, 2));
        float nm0 = fmaxf(m0, mx0), nm1 = fmaxf(m1, mx1);
        float c0 = fexp2(m0 - nm0), c1 = fexp2(m1 - nm1);
        float sum0 = 0.f, sum1 = 0.f;
#pragma unroll
        for (int na = 0; na < 8; na++) {
            s[na][0] = fexp2(s[na][0] - nm0); sum0 += s[na][0];
            s[na][1] = fexp2(s[na][1] - nm0); sum0 += s[na][1];
            s[na][2] = fexp2(s[na][2] - nm1); sum1 += s[na][2];
            s[na][3] = fexp2(s[na][3] - nm1); sum1 += s[na][3];
        }
        sum0 += __shfl_xor_sync(0xffffffffu, sum0, 1);
        sum0 += __shfl_xor_sync(0xffffffffu, sum0, 2);
        sum1 += __shfl_xor_sync(0xffffffffu, sum1, 1);
        sum1 += __shfl_xor_sync(0xffffffffu, sum1, 2);
        l0 = l0 * c0 + sum0;
        l1 = l1 * c1 + sum1;
        m0 = nm0; m1 = nm1;

        // ---- rescale O ----
#pragma unroll
        for (int na = 0; na < 16; na++) {
            o[na][0] *= c0; o[na][1] *= c0;
            o[na][2] *= c1; o[na][3] *= c1;
        }

        // ---- restage P (C-frag -> A-frag), per-warp region ----
        unsigned* pfw = PF + warp * 1024;
        {
            int la  = gid * 4;
            int c0i = (tig * 2) & 3,     c0h = (tig * 2) >> 2;
            int c1i = (tig * 2 + 1) & 3, c1h = (tig * 2 + 1) >> 2;
#pragma unroll
            for (int na = 0; na < 8; na++) {
                pfw[na * 128 + (la + c0i) * 4 + 0 + 2 * c0h] = f2tf(s[na][0]);
                pfw[na * 128 + (la + c1i) * 4 + 0 + 2 * c1h] = f2tf(s[na][1]);
                pfw[na * 128 + (la + c0i) * 4 + 1 + 2 * c0h] = f2tf(s[na][2]);
                pfw[na * 128 + (la + c1i) * 4 + 1 + 2 * c1h] = f2tf(s[na][3]);
            }
        }
        __syncwarp();

        // ---- O += P V ----
#pragma unroll
        for (int ka = 0; ka < 8; ka++) {
            unsigned pa[4];
            *(uint4*)pa = *(const uint4*)&pfw[ka * 128 + lane * 4];
#pragma unroll
            for (int na = 0; na < 16; na++) {
                unsigned bf[2];
                *(uint2*)bf = *(const uint2*)&VFc[(ka * 16 + na) * 64 + lane * 2];
                mma8(o[na], pa, bf);
            }
        }
        __syncthreads();   // next-tile buffers fully staged; cur buffers free
    }

    // ---- epilogue: O / l ----
    float r0i = 1.f / l0, r1i = 1.f / l1;
    float* Ob = Op + ((size_t)(b * NEWLEN + q0 + warp * 16)) * D_MODEL + h * DKDIM;
#pragma unroll
    for (int na = 0; na < 16; na++) {
        int c = na * 8 + tig * 2;
        *(float2*)&Ob[(size_t)gid * D_MODEL + c]       = make_float2(o[na][0] * r0i, o[na][1] * r0i);
        *(float2*)&Ob[(size_t)(gid + 8) * D_MODEL + c] = make_float2(o[na][2] * r1i, o[na][3] * r1i);
    }
}

// ---------------------------------------------------------------------------
// Launch
// ---------------------------------------------------------------------------
extern "C" void kernel_launch(void* const* d_in, const int* in_sizes, int n_in,
                              void* d_out, int out_size) {
    const float* x     = (const float*)d_in[0];
    const float* pastK = (const float*)d_in[1];
    const float* pastV = (const float*)d_in[2];
    const float* Wq    = (const float*)d_in[3];
    const float* Wk    = (const float*)d_in[4];
    const float* Wv    = (const float*)d_in[5];
    const float* Wo    = (const float*)d_in[6];
    float* out = (float*)d_out;

    float *q, *k, *v, *o;
    cudaGetSymbolAddress((void**)&q, g_q);
    cudaGetSymbolAddress((void**)&k, g_k);
    cudaGetSymbolAddress((void**)&v, g_v);
    cudaGetSymbolAddress((void**)&o, g_o);

    cudaFuncSetAttribute(gemm_qkv, cudaFuncAttributeMaxDynamicSharedMemorySize, GEMM_SMEM_BYTES);
    cudaFuncSetAttribute(gemm_one, cudaFuncAttributeMaxDynamicSharedMemorySize, GEMM_SMEM_BYTES);
    cudaFuncSetAttribute(attn_tf32, cudaFuncAttributeMaxDynamicSharedMemorySize, ATTN_SMEM_BYTES);

    dim3 qkv_grid(D_MODEL / 128, MROWS / 128, 3);   // (16, 32, 3)
    gemm_qkv<<<qkv_grid, 256, GEMM_SMEM_BYTES>>>(x, Wq, Wk, Wv, q, k, v);

    attn_tf32<<<dim3(NEWLEN / QT, NH, BATCH), 256, ATTN_SMEM_BYTES>>>(q, k, v, pastK, pastV, o);

    dim3 gemm_grid(D_MODEL / 128, MROWS / 128);     // (16, 32)
    gemm_one<<<gemm_grid, 256, GEMM_SMEM_BYTES>>>(o, Wo, out);
}

// round 6
// speedup vs baseline: 4.1731x; 1.5463x over previous
#include <cuda_runtime.h>
#include <math.h>
#include <stdint.h>

#define D_MODEL 2048
#define NH      16
#define DKDIM   128
#define BATCH   2
#define NEWLEN  2048
#define PASTLEN 2048
#define MROWS   (BATCH * NEWLEN)   // 4096

// ---------------------------------------------------------------------------
// Scratch (device globals: allocation-free, harness-legal)
// ---------------------------------------------------------------------------
__device__ float g_q[(size_t)MROWS * D_MODEL];
__device__ float g_k[(size_t)MROWS * D_MODEL];
__device__ float g_v[(size_t)MROWS * D_MODEL];
__device__ float g_o[(size_t)MROWS * D_MODEL];

// ---------------------------------------------------------------------------
// Helpers
// ---------------------------------------------------------------------------
// pack two f32 -> f16x2 (lo = first arg)
__device__ __forceinline__ unsigned f2h2(float lo, float hi) {
    unsigned u;
    asm("cvt.rn.f16x2.f32 %0, %1, %2;" : "=r"(u) : "f"(hi), "f"(lo));
    return u;
}

__device__ __forceinline__ float fexp2(float x) {
    float y;
    asm("ex2.approx.ftz.f32 %0, %1;" : "=f"(y) : "f"(x));
    return y;
}

// D += A*B  (m16n8k16, f16 inputs, fp32 accum)
__device__ __forceinline__ void mma16(float* d, const unsigned* a, const unsigned* b) {
    asm volatile(
        "mma.sync.aligned.m16n8k16.row.col.f32.f16.f16.f32 "
        "{%0,%1,%2,%3}, {%4,%5,%6,%7}, {%8,%9}, {%0,%1,%2,%3};\n"
        : "+f"(d[0]), "+f"(d[1]), "+f"(d[2]), "+f"(d[3])
        : "r"(a[0]), "r"(a[1]), "r"(a[2]), "r"(a[3]), "r"(b[0]), "r"(b[1]));
}

// Fragment maps (m16n8k16 f16), g = lane>>2, t = lane&3:
//  A (16m x 16k): a0={A[g][2t],A[g][2t+1]}  a1=rows g+8  a2=cols+8  a3=both
//    smem atom = 128 words: word = lane*4 + reg;  for (r,kk):
//    lane=(r&7)*4+((kk&7)>>1), reg=(r>>3)+2*(kk>>3), half=kk&1
//  B (16k x 8n):  b0={B[2t][g],B[2t+1][g]}  b1=k+8
//    smem atom = 64 words: word = lane*2 + reg; for (n,kk):
//    lane=(n&7)*4+((kk&7)>>1), reg=kk>>3, half=kk&1
//  C (16x8): c0=(g,2t) c1=(g,2t+1) c2=(g+8,2t) c3=(g+8,2t+1)

// ---------------------------------------------------------------------------
// FP16 GEMM body (NT): C[m][n] = sum_k A[m][k]*B[n][k]
// Block 128x128x32, 256 threads, warps 2(m) x 4(n), warp tile 64x32.
// Double-buffered fragment smem (half2 packed), 1 sync/iter.
// ---------------------------------------------------------------------------
#define GEMM_BUF_WORDS 4096                      // AF 2048 + BF 2048
#define GEMM_SMEM_BYTES (2 * GEMM_BUF_WORDS * 4) // 32 KB

__device__ __forceinline__ void gemm_body(const float* __restrict__ A,
                                          const float* __restrict__ B,
                                          float* __restrict__ C,
                                          unsigned* sg, int m0, int n0) {
    const int K = D_MODEL, N = D_MODEL;
    const int tid  = threadIdx.x;
    const int lane = tid & 31;
    const int warp = tid >> 5;
    const int wm   = warp >> 2;
    const int wn   = warp & 3;
    const int gid  = lane >> 2;
    const int tig  = lane & 3;

    const int srow = tid >> 3;         // 0..31
    const int skq  = (tid & 7) << 2;   // 0..28

    auto ldch = [&](int ch, int ktn, float4& a4, float4& b4) {
        int row = srow + 32 * ch;
        a4 = *(const float4*)(A + (size_t)(m0 + row) * K + ktn * 32 + skq);
        b4 = *(const float4*)(B + (size_t)(n0 + row) * K + ktn * 32 + skq);
    };
    auto stch = [&](int ch, unsigned* AFn, unsigned* BFn, const float4& a4, const float4& b4) {
        int row = srow + 32 * ch;
        int ma = row >> 4, ra = row & 15;
        int na = row >> 3, nn = row & 7;
        float av[4] = {a4.x, a4.y, a4.z, a4.w};
        float bv[4] = {b4.x, b4.y, b4.z, b4.w};
#pragma unroll
        for (int p = 0; p < 2; p++) {
            int c = skq + 2 * p, katom = c >> 4, kk = c & 15;
            AFn[(katom * 8 + ma) * 128 + ((ra & 7) * 4 + ((kk & 7) >> 1)) * 4 + (ra >> 3) + 2 * (kk >> 3)] =
                f2h2(av[2 * p], av[2 * p + 1]);
            BFn[(katom * 16 + na) * 64 + (nn * 4 + ((kk & 7) >> 1)) * 2 + (kk >> 3)] =
                f2h2(bv[2 * p], bv[2 * p + 1]);
        }
    };

    float acc[4][4][4];
#pragma unroll
    for (int i = 0; i < 4; i++)
#pragma unroll
        for (int j = 0; j < 4; j++)
#pragma unroll
            for (int r = 0; r < 4; r++) acc[i][j][r] = 0.f;

    // prologue: stage k-tile 0 into buffer 0
#pragma unroll
    for (int ch = 0; ch < 4; ch++) {
        float4 a4, b4;
        ldch(ch, 0, a4, b4);
        stch(ch, sg, sg + 2048, a4, b4);
    }
    __syncthreads();

    const int NKT = K / 32;
    for (int kt = 0; kt < NKT; kt++) {
        unsigned* AFc = sg + (kt & 1) * GEMM_BUF_WORDS;
        unsigned* BFc = AFc + 2048;
        unsigned* AFn = sg + ((kt & 1) ^ 1) * GEMM_BUF_WORDS;
        unsigned* BFn = AFn + 2048;
        const bool more = (kt + 1 < NKT);

#pragma unroll
        for (int ka = 0; ka < 2; ka++) {
            float4 pa0, pb0, pa1, pb1;
            if (more) { ldch(2 * ka, kt + 1, pa0, pb0); ldch(2 * ka + 1, kt + 1, pa1, pb1); }

            unsigned af[4][4], bf[4][2];
#pragma unroll
            for (int i = 0; i < 4; i++)
                *(uint4*)af[i] = *(const uint4*)&AFc[(ka * 8 + wm * 4 + i) * 128 + lane * 4];
#pragma unroll
            for (int j = 0; j < 4; j++)
                *(uint2*)bf[j] = *(const uint2*)&BFc[(ka * 16 + wn * 4 + j) * 64 + lane * 2];
#pragma unroll
            for (int i = 0; i < 4; i++)
#pragma unroll
                for (int j = 0; j < 4; j++) mma16(acc[i][j], af[i], bf[j]);

            if (more) { stch(2 * ka, AFn, BFn, pa0, pb0); stch(2 * ka + 1, AFn, BFn, pa1, pb1); }
        }
        __syncthreads();
    }

#pragma unroll
    for (int i = 0; i < 4; i++) {
        int r0 = m0 + wm * 64 + i * 16 + gid;
#pragma unroll
        for (int j = 0; j < 4; j++) {
            int cc = n0 + wn * 32 + j * 8 + tig * 2;
            *(float2*)&C[(size_t)r0 * N + cc]       = make_float2(acc[i][j][0], acc[i][j][1]);
            *(float2*)&C[(size_t)(r0 + 8) * N + cc] = make_float2(acc[i][j][2], acc[i][j][3]);
        }
    }
}

__global__ __launch_bounds__(256, 2) void gemm_qkv(const float* __restrict__ x,
                                                   const float* __restrict__ Wq,
                                                   const float* __restrict__ Wk,
                                                   const float* __restrict__ Wv,
                                                   float* __restrict__ q,
                                                   float* __restrict__ k,
                                                   float* __restrict__ v) {
    extern __shared__ unsigned sg[];
    const float* B = (blockIdx.z == 0) ? Wq : (blockIdx.z == 1) ? Wk : Wv;
    float* C = (blockIdx.z == 0) ? q : (blockIdx.z == 1) ? k : v;
    gemm_body(x, B, C, sg, blockIdx.y * 128, blockIdx.x * 128);
}

__global__ __launch_bounds__(256, 2) void gemm_one(const float* __restrict__ A,
                                                   const float* __restrict__ B,
                                                   float* __restrict__ C) {
    extern __shared__ unsigned sg[];
    gemm_body(A, B, C, sg, blockIdx.y * 128, blockIdx.x * 128);
}

// ---------------------------------------------------------------------------
// Flash attention, fp16 m16n8k16, double-buffered K/V fragment staging.
// Grid (NEWLEN/128, NH, BATCH), 256 threads (8 warps), warp owns 16 q rows.
// smem words: [buf: KF 4096 | VF 4096] x2, PF 4096  (80 KB)
// ---------------------------------------------------------------------------
#define QT 128
#define KT 64
#define ATTN_BUF_WORDS 8192
#define ATTN_SMEM_BYTES ((2 * ATTN_BUF_WORDS + 4096) * 4)   // 81920

__global__ __launch_bounds__(256, 1) void attn_f16(
    const float* __restrict__ Qp, const float* __restrict__ Kp,
    const float* __restrict__ Vp, const float* __restrict__ pK,
    const float* __restrict__ pV, float* __restrict__ Op) {
    extern __shared__ unsigned sm_u[];
    unsigned* PF = sm_u + 2 * ATTN_BUF_WORDS;   // [warp(8)][512]

    const int tid  = threadIdx.x;
    const int lane = tid & 31;
    const int warp = tid >> 5;
    const int gid  = lane >> 2;
    const int tig  = lane & 3;
    const int q0 = (gridDim.x - 1 - blockIdx.x) * QT;   // largest-first
    const int h  = blockIdx.y;
    const int b  = blockIdx.z;

    const float* Kn  = Kp + (size_t)b * NEWLEN * D_MODEL + h * DKDIM;
    const float* Vn  = Vp + (size_t)b * NEWLEN * D_MODEL + h * DKDIM;
    const float* pKb = pK + (size_t)(b * NH + h) * PASTLEN * DKDIM;
    const float* pVb = pV + (size_t)(b * NH + h) * PASTLEN * DKDIM;

    // ---- Q fragments in registers, scaled by 1/sqrt(dk)*log2(e) ----
    const float qscale = 0.08838834764831845f * 1.4426950408889634f;
    const float* Qb = Qp + ((size_t)(b * NEWLEN + q0 + warp * 16)) * D_MODEL + h * DKDIM;
    unsigned qf[8][4];
#pragma unroll
    for (int ka = 0; ka < 8; ka++) {
        int c0 = ka * 16 + 2 * tig;
        float2 x0 = *(const float2*)(Qb + (size_t)gid * D_MODEL + c0);
        float2 x1 = *(const float2*)(Qb + (size_t)(gid + 8) * D_MODEL + c0);
        float2 x2 = *(const float2*)(Qb + (size_t)gid * D_MODEL + c0 + 8);
        float2 x3 = *(const float2*)(Qb + (size_t)(gid + 8) * D_MODEL + c0 + 8);
        qf[ka][0] = f2h2(x0.x * qscale, x0.y * qscale);
        qf[ka][1] = f2h2(x1.x * qscale, x1.y * qscale);
        qf[ka][2] = f2h2(x2.x * qscale, x2.y * qscale);
        qf[ka][3] = f2h2(x3.x * qscale, x3.y * qscale);
    }

    float o[16][4];
#pragma unroll
    for (int na = 0; na < 16; na++)
#pragma unroll
        for (int r = 0; r < 4; r++) o[na][r] = 0.f;
    float m0 = -1e30f, m1 = -1e30f, l0 = 0.f, l1 = 0.f;

    // staging: thread -> key row kr (fixed), col group varies per chunk
    const int kr = tid & 63;
    int kb2 = 0;
    unsigned* KFn = sm_u;
    unsigned* VFn = sm_u + 4096;

    auto ld_chunk = [&](int ch, float4& kk, float4& vv) {
        int cq = (((tid >> 6) + 4 * ch) << 2);
        int kg = kb2 + kr;
        const float *ks, *vs;
        if (kg < PASTLEN) {
            ks = pKb + (size_t)kg * DKDIM + cq;
            vs = pVb + (size_t)kg * DKDIM + cq;
        } else {
            size_t off = (size_t)(kg - PASTLEN) * D_MODEL + cq;
            ks = Kn + off;
            vs = Vn + off;
        }
        kk = *(const float4*)ks;
        vv = *(const float4*)vs;
    };
    auto st_chunk = [&](int ch, const float4& kk, const float4& vv) {
        int cq = (((tid >> 6) + 4 * ch) << 2);
        float ke[4] = {kk.x, kk.y, kk.z, kk.w};
        float ve[4] = {vv.x, vv.y, vv.z, vv.w};
        // K: half2 packs consecutive d (thread-local)
#pragma unroll
        for (int p = 0; p < 2; p++) {
            int c = cq + 2 * p;
            KFn[((c >> 4) * 8 + (kr >> 3)) * 64 + ((kr & 7) * 4 + ((c & 7) >> 1)) * 2 + ((c & 15) >> 3)] =
                f2h2(ke[2 * p], ke[2 * p + 1]);
        }
        // V: half2 packs adjacent keys -> butterfly with kr^1 partner
        float pv[4];
        pv[0] = __shfl_xor_sync(0xffffffffu, ve[0], 1);
        pv[1] = __shfl_xor_sync(0xffffffffu, ve[1], 1);
        pv[2] = __shfl_xor_sync(0xffffffffu, ve[2], 1);
        pv[3] = __shfl_xor_sync(0xffffffffu, ve[3], 1);
        int base = (kr & 1) ? 2 : 0;
        int kre = kr & ~1;
#pragma unroll
        for (int qq = 0; qq < 2; qq++) {
            int c = cq + base + qq;
            float lo = (kr & 1) ? pv[base + qq] : ve[base + qq];   // V[kre][c]
            float hi = (kr & 1) ? ve[base + qq] : pv[base + qq];   // V[kre+1][c]
            VFn[((kre >> 4) * 16 + (c >> 3)) * 64 + ((c & 7) * 4 + ((kre & 7) >> 1)) * 2 + ((kre & 15) >> 3)] =
                f2h2(lo, hi);
        }
    };

    // ---- prologue: stage tile 0 into buffer 0 ----
#pragma unroll
    for (int ch = 0; ch < 8; ch++) {
        float4 kk, vv;
        ld_chunk(ch, kk, vv);
        st_chunk(ch, kk, vv);
    }
    __syncthreads();

    const int nkt = (PASTLEN + q0 + QT) / KT;
    const int qa0 = PASTLEN + q0 + warp * 16 + gid;

    for (int kt = 0; kt < nkt; kt++) {
        const int kb = kt * KT;
        const int cur = kt & 1;
        unsigned* KFc = sm_u + cur * ATTN_BUF_WORDS;
        unsigned* VFc = KFc + 4096;
        KFn = sm_u + (cur ^ 1) * ATTN_BUF_WORDS;
        VFn = KFn + 4096;
        kb2 = kb + KT;
        const bool more = (kt + 1 < nkt);

        // ---- S = Q K^T, prefetch next tile interleaved ----
        float s[8][4];
#pragma unroll
        for (int na = 0; na < 8; na++)
#pragma unroll
            for (int r = 0; r < 4; r++) s[na][r] = 0.f;

#pragma unroll
        for (int ka = 0; ka < 8; ka++) {
            float4 kpre, vpre;
            if (more) ld_chunk(ka, kpre, vpre);
#pragma unroll
            for (int na = 0; na < 8; na++) {
                unsigned bf[2];
                *(uint2*)bf = *(const uint2*)&KFc[(ka * 8 + na) * 64 + lane * 2];
                mma16(s[na], qf[ka], bf);
            }
            if (more) st_chunk(ka, kpre, vpre);
        }

        // ---- causal mask (C layout: key = kb + na*8 + 2t (+1), rows g / g+8) ----
        if (kb + KT - 1 > qa0) {
#pragma unroll
            for (int na = 0; na < 8; na++) {
                int key = kb + na * 8 + tig * 2;
                if (key     > qa0)     s[na][0] = -1e30f;
                if (key + 1 > qa0)     s[na][1] = -1e30f;
                if (key     > qa0 + 8) s[na][2] = -1e30f;
                if (key + 1 > qa0 + 8) s[na][3] = -1e30f;
            }
        }

        // ---- online softmax (log2 domain), 4-lane row groups ----
        float mx0 = -1e30f, mx1 = -1e30f;
#pragma unroll
        for (int na = 0; na < 8; na++) {
            mx0 = fmaxf(mx0, fmaxf(s[na][0], s[na][1]));
            mx1 = fmaxf(mx1, fmaxf(s[na][2], s[na][3]));
        }
        mx0 = fmaxf(mx0, __shfl_xor_sync(0xffffffffu, mx0, 1));
        mx0 = fmaxf(mx0, __shfl_xor_sync(0xffffffffu, mx0, 2));
        mx1 = fmaxf(mx1, __shfl_xor_sync(0xffffffffu, mx1, 1));
        mx1 = fmaxf(mx1, __shfl_xor_sync(0xffffffffu, mx1, 2));
        float nm0 = fmaxf(m0, mx0), nm1 = fmaxf(m1, mx1);
        float c0 = fexp2(m0 - nm0), c1 = fexp2(m1 - nm1);
        float sum0 = 0.f, sum1 = 0.f;
#pragma unroll
        for (int na = 0; na < 8; na++) {
            s[na][0] = fexp2(s[na][0] - nm0); sum0 += s[na][0];
            s[na][1] = fexp2(s[na][1] - nm0); sum0 += s[na][1];
            s[na][2] = fexp2(s[na][2] - nm1); sum1 += s[na][2];
            s[na][3] = fexp2(s[na][3] - nm1); sum1 += s[na][3];
        }
        sum0 += __shfl_xor_sync(0xffffffffu, sum0, 1);
        sum0 += __shfl_xor_sync(0xffffffffu, sum0, 2);
        sum1 += __shfl_xor_sync(0xffffffffu, sum1, 1);
        sum1 += __shfl_xor_sync(0xffffffffu, sum1, 2);
        l0 = l0 * c0 + sum0;
        l1 = l1 * c1 + sum1;
        m0 = nm0; m1 = nm1;

        // ---- rescale O ----
#pragma unroll
        for (int na = 0; na < 16; na++) {
            o[na][0] *= c0; o[na][1] *= c0;
            o[na][2] *= c1; o[na][3] *= c1;
        }

        // ---- restage P as f16 A-frags (half2 packs key pairs, thread-local) ----
        unsigned* pfw = PF + warp * 512;
        {
            int wbase = (gid * 4 + tig) * 4;
#pragma unroll
            for (int na = 0; na < 8; na++) {
                int w = (na >> 1) * 128 + wbase + 2 * (na & 1);
                pfw[w]     = f2h2(s[na][0], s[na][1]);   // row g
                pfw[w + 1] = f2h2(s[na][2], s[na][3]);   // row g+8
            }
        }
        __syncwarp();

        // ---- O += P V ----
#pragma unroll
        for (int ka = 0; ka < 4; ka++) {
            unsigned pa[4];
            *(uint4*)pa = *(const uint4*)&pfw[ka * 128 + lane * 4];
#pragma unroll
            for (int na = 0; na < 16; na++) {
                unsigned bf[2];
                *(uint2*)bf = *(const uint2*)&VFc[(ka * 16 + na) * 64 + lane * 2];
                mma16(o[na], pa, bf);
            }
        }
        __syncthreads();
    }

    // ---- epilogue: O / l ----
    float r0i = 1.f / l0, r1i = 1.f / l1;
    float* Ob = Op + ((size_t)(b * NEWLEN + q0 + warp * 16)) * D_MODEL + h * DKDIM;
#pragma unroll
    for (int na = 0; na < 16; na++) {
        int c = na * 8 + tig * 2;
        *(float2*)&Ob[(size_t)gid * D_MODEL + c]       = make_float2(o[na][0] * r0i, o[na][1] * r0i);
        *(float2*)&Ob[(size_t)(gid + 8) * D_MODEL + c] = make_float2(o[na][2] * r1i, o[na][3] * r1i);
    }
}

// ---------------------------------------------------------------------------
// Launch
// ---------------------------------------------------------------------------
extern "C" void kernel_launch(void* const* d_in, const int* in_sizes, int n_in,
                              void* d_out, int out_size) {
    const float* x     = (const float*)d_in[0];
    const float* pastK = (const float*)d_in[1];
    const float* pastV = (const float*)d_in[2];
    const float* Wq    = (const float*)d_in[3];
    const float* Wk    = (const float*)d_in[4];
    const float* Wv    = (const float*)d_in[5];
    const float* Wo    = (const float*)d_in[6];
    float* out = (float*)d_out;

    float *q, *k, *v, *o;
    cudaGetSymbolAddress((void**)&q, g_q);
    cudaGetSymbolAddress((void**)&k, g_k);
    cudaGetSymbolAddress((void**)&v, g_v);
    cudaGetSymbolAddress((void**)&o, g_o);

    cudaFuncSetAttribute(gemm_qkv, cudaFuncAttributeMaxDynamicSharedMemorySize, GEMM_SMEM_BYTES);
    cudaFuncSetAttribute(gemm_one, cudaFuncAttributeMaxDynamicSharedMemorySize, GEMM_SMEM_BYTES);
    cudaFuncSetAttribute(attn_f16, cudaFuncAttributeMaxDynamicSharedMemorySize, ATTN_SMEM_BYTES);

    dim3 qkv_grid(D_MODEL / 128, MROWS / 128, 3);   // (16, 32, 3)
    gemm_qkv<<<qkv_grid, 256, GEMM_SMEM_BYTES>>>(x, Wq, Wk, Wv, q, k, v);

    attn_f16<<<dim3(NEWLEN / QT, NH, BATCH), 256, ATTN_SMEM_BYTES>>>(q, k, v, pastK, pastV, o);

    dim3 gemm_grid(D_MODEL / 128, MROWS / 128);     // (16, 32)
    gemm_one<<<gemm_grid, 256, GEMM_SMEM_BYTES>>>(o, Wo, out);
}

// round 8
// speedup vs baseline: 8.0272x; 1.9235x over previous
#include <cuda_runtime.h>
#include <cuda_fp16.h>
#include <math.h>
#include <stdint.h>

#define D_MODEL 2048
#define NH      16
#define DKDIM   128
#define BATCH   2
#define NEWLEN  2048
#define PASTLEN 2048
#define MROWS   (BATCH * NEWLEN)   // 4096
#define ACT_ELEMS ((size_t)MROWS * D_MODEL)            // 8M
#define KV_ELEMS  ((size_t)BATCH * NH * PASTLEN * DKDIM) // 8M
#define W_ELEMS   ((size_t)D_MODEL * D_MODEL)          // 4M

// ---------------------------------------------------------------------------
// Scratch (device globals: allocation-free, harness-legal). All fp16.
// ---------------------------------------------------------------------------
__device__ __half g_xh[ACT_ELEMS];
__device__ __half g_pkh[KV_ELEMS];
__device__ __half g_pvh[KV_ELEMS];
__device__ __half g_wqh[W_ELEMS];
__device__ __half g_wkh[W_ELEMS];
__device__ __half g_wvh[W_ELEMS];
__device__ __half g_woh[W_ELEMS];
__device__ __half g_qh[ACT_ELEMS];
__device__ __half g_kh[ACT_ELEMS];
__device__ __half g_vh[ACT_ELEMS];
__device__ __half g_oh[ACT_ELEMS];

// ---------------------------------------------------------------------------
// Helpers
// ---------------------------------------------------------------------------
__device__ __forceinline__ unsigned f2h2(float lo, float hi) {
    unsigned u;
    asm("cvt.rn.f16x2.f32 %0, %1, %2;" : "=r"(u) : "f"(hi), "f"(lo));
    return u;
}

__device__ __forceinline__ float fexp2(float x) {
    float y;
    asm("ex2.approx.ftz.f32 %0, %1;" : "=f"(y) : "f"(x));
    return y;
}

__device__ __forceinline__ uint32_t smem_u32(const void* p) {
    uint32_t a;
    asm("{ .reg .u64 t; cvta.to.shared.u64 t, %1; cvt.u32.u64 %0, t; }" : "=r"(a) : "l"(p));
    return a;
}

__device__ __forceinline__ void mma16(float* d, const unsigned* a, const unsigned* b) {
    asm volatile(
        "mma.sync.aligned.m16n8k16.row.col.f32.f16.f16.f32 "
        "{%0,%1,%2,%3}, {%4,%5,%6,%7}, {%8,%9}, {%0,%1,%2,%3};\n"
        : "+f"(d[0]), "+f"(d[1]), "+f"(d[2]), "+f"(d[3])
        : "r"(a[0]), "r"(a[1]), "r"(a[2]), "r"(a[3]), "r"(b[0]), "r"(b[1]));
}

__device__ __forceinline__ void ldsm4(unsigned* r, uint32_t a) {
    asm volatile("ldmatrix.sync.aligned.m8n8.x4.shared.b16 {%0,%1,%2,%3}, [%4];"
                 : "=r"(r[0]), "=r"(r[1]), "=r"(r[2]), "=r"(r[3]) : "r"(a));
}
__device__ __forceinline__ void ldsm2(unsigned* r, uint32_t a) {
    asm volatile("ldmatrix.sync.aligned.m8n8.x2.shared.b16 {%0,%1}, [%2];"
                 : "=r"(r[0]), "=r"(r[1]) : "r"(a));
}
__device__ __forceinline__ void ldsm2t(unsigned* r, uint32_t a) {
    asm volatile("ldmatrix.sync.aligned.m8n8.x2.trans.shared.b16 {%0,%1}, [%2];"
                 : "=r"(r[0]), "=r"(r[1]) : "r"(a));
}

__device__ __forceinline__ void cp16(uint32_t dst, const void* src) {
    asm volatile("cp.async.cg.shared.global [%0], [%1], 16;"
                 :: "r"(dst), "l"((size_t)__cvta_generic_to_global(src)));
}
#define CP_COMMIT() asm volatile("cp.async.commit_group;" ::: "memory")
#define CP_WAIT(n)  asm volatile("cp.async.wait_group %0;" :: "n"(n) : "memory")

// ---------------------------------------------------------------------------
// fp32 -> fp16 conversion
// ---------------------------------------------------------------------------
__global__ void cvt16(const float4* __restrict__ s, __half2* __restrict__ d, int n4) {
    int i = blockIdx.x * blockDim.x + threadIdx.x;
    if (i < n4) {
        float4 v = s[i];
        d[2 * i]     = __floats2half2_rn(v.x, v.y);
        d[2 * i + 1] = __floats2half2_rn(v.z, v.w);
    }
}

// ---------------------------------------------------------------------------
// FP16 GEMM (NT): C[m][n] = sum_k A[m][k]*B[n][k];  A,B fp16, C fp16 or fp32.
// Block 128x128x32, 256 threads, warps 2(m) x 4(n), warp tile 64x32.
// 4-stage cp.async pipeline, ldmatrix fragment loads, 1 sync/iter.
// ---------------------------------------------------------------------------
#define BK 32
#define APITCH 40                                 // halves per row (pad 8)
#define GTILE_BYTES (128 * APITCH * 2)            // 10240
#define GSTAGE_BYTES (2 * GTILE_BYTES)            // 20480 (A then B)
#define GPIPE 4
#define GEMM_SMEM_BYTES (GPIPE * GSTAGE_BYTES)    // 81920

template <bool HALF_OUT>
__device__ __forceinline__ void gemm_body(const __half* __restrict__ A,
                                          const __half* __restrict__ B,
                                          void* __restrict__ Cv,
                                          char* smem, int m0, int n0) {
    const uint32_t sb = smem_u32(smem);
    const int K = D_MODEL, N = D_MODEL;
    const int tid  = threadIdx.x;
    const int lane = tid & 31;
    const int warp = tid >> 5;
    const int wm   = warp >> 2;
    const int wn   = warp & 3;
    const int gid  = lane >> 2;
    const int tig  = lane & 3;

    auto issue = [&](int kt, int s) {
        uint32_t base = sb + s * GSTAGE_BYTES;
#pragma unroll
        for (int i = 0; i < 2; i++) {
            int c = tid + i * 256;               // 0..511
            int row  = c >> 2;                   // 0..127
            int colh = (c & 3) << 3;             // 0,8,16,24
            uint32_t d = base + (row * APITCH + colh) * 2;
            cp16(d, A + (size_t)(m0 + row) * K + kt * BK + colh);
            cp16(d + GTILE_BYTES, B + (size_t)(n0 + row) * K + kt * BK + colh);
        }
        CP_COMMIT();
    };

    float acc[4][4][4];
#pragma unroll
    for (int i = 0; i < 4; i++)
#pragma unroll
        for (int j = 0; j < 4; j++)
#pragma unroll
            for (int r = 0; r < 4; r++) acc[i][j][r] = 0.f;

    issue(0, 0); issue(1, 1); issue(2, 2);

    const int NKT = K / BK;   // 64
    for (int kt = 0; kt < NKT; kt++) {
        if (kt < NKT - 2)      CP_WAIT(2);
        else if (kt < NKT - 1) CP_WAIT(1);
        else                   CP_WAIT(0);
        __syncthreads();
        if (kt + 3 < NKT) issue(kt + 3, (kt + 3) & 3);

        uint32_t abase = sb + (kt & 3) * GSTAGE_BYTES;
        uint32_t bbase = abase + GTILE_BYTES;
#pragma unroll
        for (int ka = 0; ka < 2; ka++) {
            unsigned af[4][4], bf[4][2];
#pragma unroll
            for (int i = 0; i < 4; i++) {
                int row  = wm * 64 + i * 16 + (lane & 15);
                int colh = ka * 16 + ((lane >> 4) << 3);
                ldsm4(af[i], abase + (row * APITCH + colh) * 2);
            }
#pragma unroll
            for (int j = 0; j < 4; j++) {
                int nrow = wn * 32 + j * 8 + (lane & 7);
                int colh = ka * 16 + (((lane >> 3) & 1) << 3);
                ldsm2(bf[j], bbase + (nrow * APITCH + colh) * 2);
            }
#pragma unroll
            for (int i = 0; i < 4; i++)
#pragma unroll
                for (int j = 0; j < 4; j++) mma16(acc[i][j], af[i], bf[j]);
        }
    }

#pragma unroll
    for (int i = 0; i < 4; i++) {
        int r0 = m0 + wm * 64 + i * 16 + gid;
#pragma unroll
        for (int j = 0; j < 4; j++) {
            int cc = n0 + wn * 32 + j * 8 + tig * 2;
            if (HALF_OUT) {
                __half* C = (__half*)Cv;
                *(unsigned*)(C + (size_t)r0 * N + cc)       = f2h2(acc[i][j][0], acc[i][j][1]);
                *(unsigned*)(C + (size_t)(r0 + 8) * N + cc) = f2h2(acc[i][j][2], acc[i][j][3]);
            } else {
                float* C = (float*)Cv;
                *(float2*)&C[(size_t)r0 * N + cc]       = make_float2(acc[i][j][0], acc[i][j][1]);
                *(float2*)&C[(size_t)(r0 + 8) * N + cc] = make_float2(acc[i][j][2], acc[i][j][3]);
            }
        }
    }
}

__global__ __launch_bounds__(256, 2) void gemm_qkv(const __half* __restrict__ x,
                                                   const __half* __restrict__ Wq,
                                                   const __half* __restrict__ Wk,
                                                   const __half* __restrict__ Wv,
                                                   __half* __restrict__ q,
                                                   __half* __restrict__ k,
                                                   __half* __restrict__ v) {
    extern __shared__ char sg[];
    const __half* B = (blockIdx.z == 0) ? Wq : (blockIdx.z == 1) ? Wk : Wv;
    __half* C = (blockIdx.z == 0) ? q : (blockIdx.z == 1) ? k : v;
    gemm_body<true>(x, B, C, sg, blockIdx.y * 128, blockIdx.x * 128);
}

__global__ __launch_bounds__(256, 2) void gemm_out(const __half* __restrict__ A,
                                                   const __half* __restrict__ B,
                                                   float* __restrict__ C) {
    extern __shared__ char sg[];
    gemm_body<false>(A, B, C, sg, blockIdx.y * 128, blockIdx.x * 128);
}

// ---------------------------------------------------------------------------
// Flash attention, fp16 m16n8k16, cp.async 3-stage K/V pipeline + ldmatrix.
// Grid (NEWLEN/128, NH, BATCH), 256 threads (8 warps), warp owns 16 q rows.
// ---------------------------------------------------------------------------
#define QT 128
#define KT 64
#define KVPITCH 136                               // halves per row (pad 8)
#define KVTILE_BYTES (KT * KVPITCH * 2)           // 17408
#define ASTAGE_BYTES (2 * KVTILE_BYTES)           // 34816 (K then V)
#define APIPE 3
#define PF_BYTES (8 * 512 * 4)                    // 16384
#define ATTN_SMEM_BYTES (APIPE * ASTAGE_BYTES + PF_BYTES)  // 120832

__global__ __launch_bounds__(256, 1) void attn_f16(
    const __half* __restrict__ qh, const __half* __restrict__ kh,
    const __half* __restrict__ vh, const __half* __restrict__ pkh,
    const __half* __restrict__ pvh, __half* __restrict__ oh) {
    extern __shared__ char smem[];
    const uint32_t sb = smem_u32(smem);
    unsigned* PF = (unsigned*)(smem + APIPE * ASTAGE_BYTES);

    const int tid  = threadIdx.x;
    const int lane = tid & 31;
    const int warp = tid >> 5;
    const int gid  = lane >> 2;
    const int tig  = lane & 3;
    const int q0 = (gridDim.x - 1 - blockIdx.x) * QT;   // largest-first
    const int h  = blockIdx.y;
    const int b  = blockIdx.z;

    const __half* Kn  = kh + (size_t)b * NEWLEN * D_MODEL + h * DKDIM;
    const __half* Vn  = vh + (size_t)b * NEWLEN * D_MODEL + h * DKDIM;
    const __half* pKb = pkh + (size_t)(b * NH + h) * PASTLEN * DKDIM;
    const __half* pVb = pvh + (size_t)(b * NH + h) * PASTLEN * DKDIM;

    // ---- Q fragments straight from fp16 global ----
    const __half* Qb = qh + ((size_t)(b * NEWLEN + q0 + warp * 16)) * D_MODEL + h * DKDIM;
    unsigned qf[8][4];
#pragma unroll
    for (int ka = 0; ka < 8; ka++) {
        int c0 = ka * 16 + 2 * tig;
        qf[ka][0] = *(const unsigned*)(Qb + (size_t)gid * D_MODEL + c0);
        qf[ka][1] = *(const unsigned*)(Qb + (size_t)(gid + 8) * D_MODEL + c0);
        qf[ka][2] = *(const unsigned*)(Qb + (size_t)gid * D_MODEL + c0 + 8);
        qf[ka][3] = *(const unsigned*)(Qb + (size_t)(gid + 8) * D_MODEL + c0 + 8);
    }

    float o[16][4];
#pragma unroll
    for (int na = 0; na < 16; na++)
#pragma unroll
        for (int r = 0; r < 4; r++) o[na][r] = 0.f;
    float m0 = -1e30f, m1 = -1e30f, l0 = 0.f, l1 = 0.f;

    auto issue = [&](int kt, int s) {
        uint32_t base = sb + s * ASTAGE_BYTES;
        int kb = kt * KT;
#pragma unroll
        for (int i = 0; i < 4; i++) {
            int c = tid + i * 256;               // 0..1023
            int row  = c >> 4;                   // 0..63
            int colh = (c & 15) << 3;            // 0..120
            int kg = kb + row;
            const __half *ks, *vs;
            if (kg < PASTLEN) {
                ks = pKb + (size_t)kg * DKDIM + colh;
                vs = pVb + (size_t)kg * DKDIM + colh;
            } else {
                size_t off = (size_t)(kg - PASTLEN) * D_MODEL + colh;
                ks = Kn + off;
                vs = Vn + off;
            }
            uint32_t d = base + (row * KVPITCH + colh) * 2;
            cp16(d, ks);
            cp16(d + KVTILE_BYTES, vs);
        }
        CP_COMMIT();
    };

    const int nkt = (PASTLEN + q0 + QT) / KT;
    const int qa0 = PASTLEN + q0 + warp * 16 + gid;
    const float SCL = 0.08838834764831845f * 1.4426950408889634f;  // 1/sqrt(dk)*log2e

    issue(0, 0);
    if (nkt > 1) issue(1, 1);

    int scur = 0;
    for (int kt = 0; kt < nkt; kt++) {
        if (kt < nkt - 1) CP_WAIT(1);
        else              CP_WAIT(0);
        __syncthreads();
        if (kt + 2 < nkt) {
            int s2 = scur + 2; if (s2 >= APIPE) s2 -= APIPE;
            issue(kt + 2, s2);
        }
        const int kb = kt * KT;
        uint32_t kbase = sb + scur * ASTAGE_BYTES;
        uint32_t vbase = kbase + KVTILE_BYTES;

        // ---- S = Q K^T ----
        float s_[8][4];
#pragma unroll
        for (int na = 0; na < 8; na++)
#pragma unroll
            for (int r = 0; r < 4; r++) s_[na][r] = 0.f;
#pragma unroll
        for (int ka = 0; ka < 8; ka++) {
#pragma unroll
            for (int na = 0; na < 8; na++) {
                unsigned bf[2];
                int krow = na * 8 + (lane & 7);
                int colh = ka * 16 + (((lane >> 3) & 1) << 3);
                ldsm2(bf, kbase + (krow * KVPITCH + colh) * 2);
                mma16(s_[na], qf[ka], bf);
            }
        }
#pragma unroll
        for (int na = 0; na < 8; na++)
#pragma unroll
            for (int r = 0; r < 4; r++) s_[na][r] *= SCL;

        // ---- causal mask ----
        if (kb + KT - 1 > qa0) {
#pragma unroll
            for (int na = 0; na < 8; na++) {
                int key = kb + na * 8 + tig * 2;
                if (key     > qa0)     s_[na][0] = -1e30f;
                if (key + 1 > qa0)     s_[na][1] = -1e30f;
                if (key     > qa0 + 8) s_[na][2] = -1e30f;
                if (key + 1 > qa0 + 8) s_[na][3] = -1e30f;
            }
        }

        // ---- online softmax (log2 domain), 4-lane row groups ----
        float mx0 = -1e30f, mx1 = -1e30f;
#pragma unroll
        for (int na = 0; na < 8; na++) {
            mx0 = fmaxf(mx0, fmaxf(s_[na][0], s_[na][1]));
            mx1 = fmaxf(mx1, fmaxf(s_[na][2], s_[na][3]));
        }
        mx0 = fmaxf(mx0, __shfl_xor_sync(0xffffffffu, mx0, 1));
        mx0 = fmaxf(mx0, __shfl_xor_sync(0xffffffffu, mx0, 2));
        mx1 = fmaxf(mx1, __shfl_xor_sync(0xffffffffu, mx1, 1));
        mx1 = fmaxf(mx1, __shfl_xor_sync(0xffffffffu, mx1, 2));
        float nm0 = fmaxf(m0, mx0), nm1 = fmaxf(m1, mx1);
        float c0 = fexp2(m0 - nm0), c1 = fexp2(m1 - nm1);
        float sum0 = 0.f, sum1 = 0.f;
#pragma unroll
        for (int na = 0; na < 8; na++) {
            s_[na][0] = fexp2(s_[na][0] - nm0); sum0 += s_[na][0];
            s_[na][1] = fexp2(s_[na][1] - nm0); sum0 += s_[na][1];
            s_[na][2] = fexp2(s_[na][2] - nm1); sum1 += s_[na][2];
            s_[na][3] = fexp2(s_[na][3] - nm1); sum1 += s_[na][3];
        }
        sum0 += __shfl_xor_sync(0xffffffffu, sum0, 1);
        sum0 += __shfl_xor_sync(0xffffffffu, sum0, 2);
        sum1 += __shfl_xor_sync(0xffffffffu, sum1, 1);
        sum1 += __shfl_xor_sync(0xffffffffu, sum1, 2);
        l0 = l0 * c0 + sum0;
        l1 = l1 * c1 + sum1;
        m0 = nm0; m1 = nm1;

        // ---- rescale O ----
#pragma unroll
        for (int na = 0; na < 16; na++) {
            o[na][0] *= c0; o[na][1] *= c0;
            o[na][2] *= c1; o[na][3] *= c1;
        }

        // ---- restage P as f16 A-frags (half2 packs key pairs) ----
        unsigned* pfw = PF + warp * 512;
        {
            int wbase = (gid * 4 + tig) * 4;
#pragma unroll
            for (int na = 0; na < 8; na++) {
                int w = (na >> 1) * 128 + wbase + 2 * (na & 1);
                pfw[w]     = f2h2(s_[na][0], s_[na][1]);   // row g
                pfw[w + 1] = f2h2(s_[na][2], s_[na][3]);   // row g+8
            }
        }
        __syncwarp();

        // ---- O += P V (V via ldmatrix.trans) ----
#pragma unroll
        for (int ka = 0; ka < 4; ka++) {
            unsigned pa[4];
            *(uint4*)pa = *(const uint4*)&pfw[ka * 128 + lane * 4];
#pragma unroll
            for (int na = 0; na < 16; na++) {
                unsigned bf[2];
                int vrow = ka * 16 + (lane & 15);
                ldsm2t(bf, vbase + (vrow * KVPITCH + na * 8) * 2);
                mma16(o[na], pa, bf);
            }
        }

        scur++; if (scur >= APIPE) scur = 0;
    }

    // ---- epilogue: O / l, fp16 out ----
    float r0i = 1.f / l0, r1i = 1.f / l1;
    __half* Ob = oh + ((size_t)(b * NEWLEN + q0 + warp * 16)) * D_MODEL + h * DKDIM;
#pragma unroll
    for (int na = 0; na < 16; na++) {
        int c = na * 8 + tig * 2;
        *(unsigned*)(Ob + (size_t)gid * D_MODEL + c)       = f2h2(o[na][0] * r0i, o[na][1] * r0i);
        *(unsigned*)(Ob + (size_t)(gid + 8) * D_MODEL + c) = f2h2(o[na][2] * r1i, o[na][3] * r1i);
    }
}

// ---------------------------------------------------------------------------
// Launch
// ---------------------------------------------------------------------------
extern "C" void kernel_launch(void* const* d_in, const int* in_sizes, int n_in,
                              void* d_out, int out_size) {
    const float* x     = (const float*)d_in[0];
    const float* pastK = (const float*)d_in[1];
    const float* pastV = (const float*)d_in[2];
    const float* Wq    = (const float*)d_in[3];
    const float* Wk    = (const float*)d_in[4];
    const float* Wv    = (const float*)d_in[5];
    const float* Wo    = (const float*)d_in[6];
    float* out = (float*)d_out;

    __half *xh, *pkh, *pvh, *wqh, *wkh, *wvh, *woh, *qh, *kh, *vh, *oh;
    cudaGetSymbolAddress((void**)&xh,  g_xh);
    cudaGetSymbolAddress((void**)&pkh, g_pkh);
    cudaGetSymbolAddress((void**)&pvh, g_pvh);
    cudaGetSymbolAddress((void**)&wqh, g_wqh);
    cudaGetSymbolAddress((void**)&wkh, g_wkh);
    cudaGetSymbolAddress((void**)&wvh, g_wvh);
    cudaGetSymbolAddress((void**)&woh, g_woh);
    cudaGetSymbolAddress((void**)&qh,  g_qh);
    cudaGetSymbolAddress((void**)&kh,  g_kh);
    cudaGetSymbolAddress((void**)&vh,  g_vh);
    cudaGetSymbolAddress((void**)&oh,  g_oh);

    cudaFuncSetAttribute(gemm_qkv, cudaFuncAttributeMaxDynamicSharedMemorySize, GEMM_SMEM_BYTES);
    cudaFuncSetAttribute(gemm_out, cudaFuncAttributeMaxDynamicSharedMemorySize, GEMM_SMEM_BYTES);
    cudaFuncSetAttribute(attn_f16, cudaFuncAttributeMaxDynamicSharedMemorySize, ATTN_SMEM_BYTES);

    // ---- fp32 -> fp16 conversions ----
    const int ACT4 = (int)(ACT_ELEMS / 4), W4 = (int)(W_ELEMS / 4);
    cvt16<<<ACT4 / 256, 256>>>((const float4*)x,     (__half2*)xh,  ACT4);
    cvt16<<<ACT4 / 256, 256>>>((const float4*)pastK, (__half2*)pkh, ACT4);
    cvt16<<<ACT4 / 256, 256>>>((const float4*)pastV, (__half2*)pvh, ACT4);
    cvt16<<<W4 / 256, 256>>>((const float4*)Wq, (__half2*)wqh, W4);
    cvt16<<<W4 / 256, 256>>>((const float4*)Wk, (__half2*)wkh, W4);
    cvt16<<<W4 / 256, 256>>>((const float4*)Wv, (__half2*)wvh, W4);
    cvt16<<<W4 / 256, 256>>>((const float4*)Wo, (__half2*)woh, W4);

    dim3 qkv_grid(D_MODEL / 128, MROWS / 128, 3);   // (16, 32, 3)
    gemm_qkv<<<qkv_grid, 256, GEMM_SMEM_BYTES>>>(xh, wqh, wkh, wvh, qh, kh, vh);

    attn_f16<<<dim3(NEWLEN / QT, NH, BATCH), 256, ATTN_SMEM_BYTES>>>(qh, kh, vh, pkh, pvh, oh);

    dim3 gemm_grid(D_MODEL / 128, MROWS / 128);     // (16, 32)
    gemm_out<<<gemm_grid, 256, GEMM_SMEM_BYTES>>>(oh, woh, out);
}

// round 9
// speedup vs baseline: 8.4460x; 1.0522x over previous
#include <cuda_runtime.h>
#include <cuda_fp16.h>
#include <math.h>
#include <stdint.h>

#define D_MODEL 2048
#define NH      16
#define DKDIM   128
#define BATCH   2
#define NEWLEN  2048
#define PASTLEN 2048
#define MROWS   (BATCH * NEWLEN)   // 4096
#define ACT_ELEMS ((size_t)MROWS * D_MODEL)              // 8M
#define KV_ELEMS  ((size_t)BATCH * NH * PASTLEN * DKDIM) // 8M
#define W_ELEMS   ((size_t)D_MODEL * D_MODEL)            // 4M

// ---------------------------------------------------------------------------
// Scratch (device globals: allocation-free, harness-legal). All fp16.
// ---------------------------------------------------------------------------
__device__ __half g_xh[ACT_ELEMS];
__device__ __half g_pkh[KV_ELEMS];
__device__ __half g_pvh[KV_ELEMS];
__device__ __half g_wqh[W_ELEMS];
__device__ __half g_wkh[W_ELEMS];
__device__ __half g_wvh[W_ELEMS];
__device__ __half g_woh[W_ELEMS];
__device__ __half g_qh[ACT_ELEMS];
__device__ __half g_kh[ACT_ELEMS];
__device__ __half g_vh[ACT_ELEMS];
__device__ __half g_oh[ACT_ELEMS];

// ---------------------------------------------------------------------------
// Helpers
// ---------------------------------------------------------------------------
__device__ __forceinline__ unsigned f2h2(float lo, float hi) {
    unsigned u;
    asm("cvt.rn.f16x2.f32 %0, %1, %2;" : "=r"(u) : "f"(hi), "f"(lo));
    return u;
}

__device__ __forceinline__ float fexp2(float x) {
    float y;
    asm("ex2.approx.ftz.f32 %0, %1;" : "=f"(y) : "f"(x));
    return y;
}

__device__ __forceinline__ uint32_t smem_u32(const void* p) {
    uint32_t a;
    asm("{ .reg .u64 t; cvta.to.shared.u64 t, %1; cvt.u32.u64 %0, t; }" : "=r"(a) : "l"(p));
    return a;
}

__device__ __forceinline__ void mma16(float* d, const unsigned* a, const unsigned* b) {
    asm volatile(
        "mma.sync.aligned.m16n8k16.row.col.f32.f16.f16.f32 "
        "{%0,%1,%2,%3}, {%4,%5,%6,%7}, {%8,%9}, {%0,%1,%2,%3};\n"
        : "+f"(d[0]), "+f"(d[1]), "+f"(d[2]), "+f"(d[3])
        : "r"(a[0]), "r"(a[1]), "r"(a[2]), "r"(a[3]), "r"(b[0]), "r"(b[1]));
}

__device__ __forceinline__ void ldsm4(unsigned* r, uint32_t a) {
    asm volatile("ldmatrix.sync.aligned.m8n8.x4.shared.b16 {%0,%1,%2,%3}, [%4];"
                 : "=r"(r[0]), "=r"(r[1]), "=r"(r[2]), "=r"(r[3]) : "r"(a));
}
__device__ __forceinline__ void ldsm4t(unsigned* r, uint32_t a) {
    asm volatile("ldmatrix.sync.aligned.m8n8.x4.trans.shared.b16 {%0,%1,%2,%3}, [%4];"
                 : "=r"(r[0]), "=r"(r[1]), "=r"(r[2]), "=r"(r[3]) : "r"(a));
}

__device__ __forceinline__ void cp16(uint32_t dst, const void* src) {
    asm volatile("cp.async.cg.shared.global [%0], [%1], 16;"
                 :: "r"(dst), "l"((size_t)__cvta_generic_to_global(src)));
}
#define CP_COMMIT() asm volatile("cp.async.commit_group;" ::: "memory")
#define CP_WAIT(n)  asm volatile("cp.async.wait_group %0;" :: "n"(n) : "memory")

// ---------------------------------------------------------------------------
// fp32 -> fp16 conversion (optional scale folded in before rounding)
// ---------------------------------------------------------------------------
__global__ void cvt16(const float4* __restrict__ s, __half2* __restrict__ d, int n4,
                      float scale) {
    int i = blockIdx.x * blockDim.x + threadIdx.x;
    if (i < n4) {
        float4 v = s[i];
        d[2 * i]     = __floats2half2_rn(v.x * scale, v.y * scale);
        d[2 * i + 1] = __floats2half2_rn(v.z * scale, v.w * scale);
    }
}

// ---------------------------------------------------------------------------
// FP16 GEMM (NT): C[m][n] = sum_k A[m][k]*B[n][k];  A,B fp16, C fp16 or fp32.
// Block 128x128x32, 256 threads, warps 2(m) x 4(n), warp tile 64x32.
// 4-stage cp.async pipeline, ldmatrix.x4 fragment loads, 1 sync/iter.
// ---------------------------------------------------------------------------
#define BK 32
#define APITCH 40                                 // halves per row (pad 8)
#define GTILE_BYTES (128 * APITCH * 2)            // 10240
#define GSTAGE_BYTES (2 * GTILE_BYTES)            // 20480 (A then B)
#define GPIPE 4
#define GEMM_SMEM_BYTES (GPIPE * GSTAGE_BYTES)    // 81920

template <bool HALF_OUT>
__device__ __forceinline__ void gemm_body(const __half* __restrict__ A,
                                          const __half* __restrict__ B,
                                          void* __restrict__ Cv,
                                          char* smem, int m0, int n0) {
    const uint32_t sb = smem_u32(smem);
    const int K = D_MODEL, N = D_MODEL;
    const int tid  = threadIdx.x;
    const int lane = tid & 31;
    const int warp = tid >> 5;
    const int wm   = warp >> 2;
    const int wn   = warp & 3;
    const int gid  = lane >> 2;
    const int tig  = lane & 3;
    const int grp  = lane >> 3;          // 0..3 (ldmatrix 8-lane groups)

    auto issue = [&](int kt, int s) {
        uint32_t base = sb + s * GSTAGE_BYTES;
#pragma unroll
        for (int i = 0; i < 2; i++) {
            int c = tid + i * 256;               // 0..511
            int row  = c >> 2;                   // 0..127
            int colh = (c & 3) << 3;             // 0,8,16,24
            uint32_t d = base + (row * APITCH + colh) * 2;
            cp16(d, A + (size_t)(m0 + row) * K + kt * BK + colh);
            cp16(d + GTILE_BYTES, B + (size_t)(n0 + row) * K + kt * BK + colh);
        }
        CP_COMMIT();
    };

    float acc[4][4][4];
#pragma unroll
    for (int i = 0; i < 4; i++)
#pragma unroll
        for (int j = 0; j < 4; j++)
#pragma unroll
            for (int r = 0; r < 4; r++) acc[i][j][r] = 0.f;

    issue(0, 0); issue(1, 1); issue(2, 2);

    const int NKT = K / BK;   // 64
    for (int kt = 0; kt < NKT; kt++) {
        if (kt < NKT - 2)      CP_WAIT(2);
        else if (kt < NKT - 1) CP_WAIT(1);
        else                   CP_WAIT(0);
        __syncthreads();
        if (kt + 3 < NKT) issue(kt + 3, (kt + 3) & 3);

        uint32_t abase = sb + (kt & 3) * GSTAGE_BYTES;
        uint32_t bbase = abase + GTILE_BYTES;
#pragma unroll
        for (int ka = 0; ka < 2; ka++) {
            unsigned af[4][4], bf[4][2];
#pragma unroll
            for (int i = 0; i < 4; i++) {
                int row  = wm * 64 + i * 16 + (lane & 15);
                int colh = ka * 16 + ((lane >> 4) << 3);
                ldsm4(af[i], abase + (row * APITCH + colh) * 2);
            }
            // B: two n-atoms per ldsm4 (m0,m1 = j k-halves; m2,m3 = j+1)
#pragma unroll
            for (int jp = 0; jp < 2; jp++) {
                unsigned b4[4];
                int j2   = 2 * jp + (grp >> 1);
                int nrow = wn * 32 + j2 * 8 + (lane & 7);
                int colh = ka * 16 + ((grp & 1) << 3);
                ldsm4(b4, bbase + (nrow * APITCH + colh) * 2);
                bf[2 * jp][0] = b4[0];     bf[2 * jp][1] = b4[1];
                bf[2 * jp + 1][0] = b4[2]; bf[2 * jp + 1][1] = b4[3];
            }
#pragma unroll
            for (int i = 0; i < 4; i++)
#pragma unroll
                for (int j = 0; j < 4; j++) mma16(acc[i][j], af[i], bf[j]);
        }
    }

#pragma unroll
    for (int i = 0; i < 4; i++) {
        int r0 = m0 + wm * 64 + i * 16 + gid;
#pragma unroll
        for (int j = 0; j < 4; j++) {
            int cc = n0 + wn * 32 + j * 8 + tig * 2;
            if (HALF_OUT) {
                __half* C = (__half*)Cv;
                *(unsigned*)(C + (size_t)r0 * N + cc)       = f2h2(acc[i][j][0], acc[i][j][1]);
                *(unsigned*)(C + (size_t)(r0 + 8) * N + cc) = f2h2(acc[i][j][2], acc[i][j][3]);
            } else {
                float* C = (float*)Cv;
                *(float2*)&C[(size_t)r0 * N + cc]       = make_float2(acc[i][j][0], acc[i][j][1]);
                *(float2*)&C[(size_t)(r0 + 8) * N + cc] = make_float2(acc[i][j][2], acc[i][j][3]);
            }
        }
    }
}

__global__ __launch_bounds__(256, 2) void gemm_qkv(const __half* __restrict__ x,
                                                   const __half* __restrict__ Wq,
                                                   const __half* __restrict__ Wk,
                                                   const __half* __restrict__ Wv,
                                                   __half* __restrict__ q,
                                                   __half* __restrict__ k,
                                                   __half* __restrict__ v) {
    extern __shared__ char sg[];
    const __half* B = (blockIdx.z == 0) ? Wq : (blockIdx.z == 1) ? Wk : Wv;
    __half* C = (blockIdx.z == 0) ? q : (blockIdx.z == 1) ? k : v;
    gemm_body<true>(x, B, C, sg, blockIdx.y * 128, blockIdx.x * 128);
}

__global__ __launch_bounds__(256, 2) void gemm_out(const __half* __restrict__ A,
                                                   const __half* __restrict__ B,
                                                   float* __restrict__ C) {
    extern __shared__ char sg[];
    gemm_body<false>(A, B, C, sg, blockIdx.y * 128, blockIdx.x * 128);
}

// ---------------------------------------------------------------------------
// Flash attention, fp16 m16n8k16, cp.async 3-stage K/V pipeline + ldmatrix.x4.
// Grid (NEWLEN/128, NH, BATCH), 256 threads (8 warps), warp owns 16 q rows.
// Q pre-scaled (scale folded into Wq at cvt time).
// ---------------------------------------------------------------------------
#define QT 128
#define KT 64
#define KVPITCH 136                               // halves per row (pad 8)
#define KVTILE_BYTES (KT * KVPITCH * 2)           // 17408
#define ASTAGE_BYTES (2 * KVTILE_BYTES)           // 34816 (K then V)
#define APIPE 3
#define PF_BYTES (8 * 512 * 4)                    // 16384
#define ATTN_SMEM_BYTES (APIPE * ASTAGE_BYTES + PF_BYTES)  // 120832

__global__ __launch_bounds__(256, 1) void attn_f16(
    const __half* __restrict__ qh, const __half* __restrict__ kh,
    const __half* __restrict__ vh, const __half* __restrict__ pkh,
    const __half* __restrict__ pvh, __half* __restrict__ oh) {
    extern __shared__ char smem[];
    const uint32_t sb = smem_u32(smem);
    unsigned* PF = (unsigned*)(smem + APIPE * ASTAGE_BYTES);

    const int tid  = threadIdx.x;
    const int lane = tid & 31;
    const int warp = tid >> 5;
    const int gid  = lane >> 2;
    const int tig  = lane & 3;
    const int grp  = lane >> 3;          // 0..3
    const int q0 = (gridDim.x - 1 - blockIdx.x) * QT;   // largest-first
    const int h  = blockIdx.y;
    const int b  = blockIdx.z;

    const __half* Kn  = kh + (size_t)b * NEWLEN * D_MODEL + h * DKDIM;
    const __half* Vn  = vh + (size_t)b * NEWLEN * D_MODEL + h * DKDIM;
    const __half* pKb = pkh + (size_t)(b * NH + h) * PASTLEN * DKDIM;
    const __half* pVb = pvh + (size_t)(b * NH + h) * PASTLEN * DKDIM;

    // ---- Q fragments straight from fp16 global (already scaled via Wq) ----
    const __half* Qb = qh + ((size_t)(b * NEWLEN + q0 + warp * 16)) * D_MODEL + h * DKDIM;
    unsigned qf[8][4];
#pragma unroll
    for (int ka = 0; ka < 8; ka++) {
        int c0 = ka * 16 + 2 * tig;
        qf[ka][0] = *(const unsigned*)(Qb + (size_t)gid * D_MODEL + c0);
        qf[ka][1] = *(const unsigned*)(Qb + (size_t)(gid + 8) * D_MODEL + c0);
        qf[ka][2] = *(const unsigned*)(Qb + (size_t)gid * D_MODEL + c0 + 8);
        qf[ka][3] = *(const unsigned*)(Qb + (size_t)(gid + 8) * D_MODEL + c0 + 8);
    }

    float o[16][4];
#pragma unroll
    for (int na = 0; na < 16; na++)
#pragma unroll
        for (int r = 0; r < 4; r++) o[na][r] = 0.f;
    float m0 = -1e30f, m1 = -1e30f, l0 = 0.f, l1 = 0.f;

    auto issue = [&](int kt, int s) {
        uint32_t base = sb + s * ASTAGE_BYTES;
        int kb = kt * KT;
#pragma unroll
        for (int i = 0; i < 4; i++) {
            int c = tid + i * 256;               // 0..1023
            int row  = c >> 4;                   // 0..63
            int colh = (c & 15) << 3;            // 0..120
            int kg = kb + row;
            const __half *ks, *vs;
            if (kg < PASTLEN) {
                ks = pKb + (size_t)kg * DKDIM + colh;
                vs = pVb + (size_t)kg * DKDIM + colh;
            } else {
                size_t off = (size_t)(kg - PASTLEN) * D_MODEL + colh;
                ks = Kn + off;
                vs = Vn + off;
            }
            uint32_t d = base + (row * KVPITCH + colh) * 2;
            cp16(d, ks);
            cp16(d + KVTILE_BYTES, vs);
        }
        CP_COMMIT();
    };

    const int nkt = (PASTLEN + q0 + QT) / KT;
    const int qa0 = PASTLEN + q0 + warp * 16 + gid;

    issue(0, 0);
    if (nkt > 1) issue(1, 1);

    int scur = 0;
    for (int kt = 0; kt < nkt; kt++) {
        if (kt < nkt - 1) CP_WAIT(1);
        else              CP_WAIT(0);
        __syncthreads();
        if (kt + 2 < nkt) {
            int s2 = scur + 2; if (s2 >= APIPE) s2 -= APIPE;
            issue(kt + 2, s2);
        }
        const int kb = kt * KT;
        uint32_t kbase = sb + scur * ASTAGE_BYTES;
        uint32_t vbase = kbase + KVTILE_BYTES;

        // ---- S = Q K^T (two n-atoms per ldsm4) ----
        float s_[8][4];
#pragma unroll
        for (int na = 0; na < 8; na++)
#pragma unroll
            for (int r = 0; r < 4; r++) s_[na][r] = 0.f;
#pragma unroll
        for (int ka = 0; ka < 8; ka++) {
#pragma unroll
            for (int nap = 0; nap < 4; nap++) {
                unsigned b4[4];
                int na2  = 2 * nap + (grp >> 1);
                int krow = na2 * 8 + (lane & 7);
                int colh = ka * 16 + ((grp & 1) << 3);
                ldsm4(b4, kbase + (krow * KVPITCH + colh) * 2);
                mma16(s_[2 * nap],     qf[ka], b4);
                mma16(s_[2 * nap + 1], qf[ka], b4 + 2);
            }
        }

        // ---- causal mask ----
        if (kb + KT - 1 > qa0) {
#pragma unroll
            for (int na = 0; na < 8; na++) {
                int key = kb + na * 8 + tig * 2;
                if (key     > qa0)     s_[na][0] = -1e30f;
                if (key + 1 > qa0)     s_[na][1] = -1e30f;
                if (key     > qa0 + 8) s_[na][2] = -1e30f;
                if (key + 1 > qa0 + 8) s_[na][3] = -1e30f;
            }
        }

        // ---- online softmax (log2 domain), 4-lane row groups ----
        float mx0 = -1e30f, mx1 = -1e30f;
#pragma unroll
        for (int na = 0; na < 8; na++) {
            mx0 = fmaxf(mx0, fmaxf(s_[na][0], s_[na][1]));
            mx1 = fmaxf(mx1, fmaxf(s_[na][2], s_[na][3]));
        }
        mx0 = fmaxf(mx0, __shfl_xor_sync(0xffffffffu, mx0, 1));
        mx0 = fmaxf(mx0, __shfl_xor_sync(0xffffffffu, mx0, 2));
        mx1 = fmaxf(mx1, __shfl_xor_sync(0xffffffffu, mx1, 1));
        mx1 = fmaxf(mx1, __shfl_xor_sync(0xffffffffu, mx1, 2));
        float nm0 = fmaxf(m0, mx0), nm1 = fmaxf(m1, mx1);
        float c0 = fexp2(m0 - nm0), c1 = fexp2(m1 - nm1);
        float sum0 = 0.f, sum1 = 0.f;
#pragma unroll
        for (int na = 0; na < 8; na++) {
            s_[na][0] = fexp2(s_[na][0] - nm0); sum0 += s_[na][0];
            s_[na][1] = fexp2(s_[na][1] - nm0); sum0 += s_[na][1];
            s_[na][2] = fexp2(s_[na][2] - nm1); sum1 += s_[na][2];
            s_[na][3] = fexp2(s_[na][3] - nm1); sum1 += s_[na][3];
        }
        sum0 += __shfl_xor_sync(0xffffffffu, sum0, 1);
        sum0 += __shfl_xor_sync(0xffffffffu, sum0, 2);
        sum1 += __shfl_xor_sync(0xffffffffu, sum1, 1);
        sum1 += __shfl_xor_sync(0xffffffffu, sum1, 2);
        l0 = l0 * c0 + sum0;
        l1 = l1 * c1 + sum1;
        m0 = nm0; m1 = nm1;

        // ---- rescale O ----
#pragma unroll
        for (int na = 0; na < 16; na++) {
            o[na][0] *= c0; o[na][1] *= c0;
            o[na][2] *= c1; o[na][3] *= c1;
        }

        // ---- restage P as f16 A-frags (half2 packs key pairs) ----
        unsigned* pfw = PF + warp * 512;
        {
            int wbase = (gid * 4 + tig) * 4;
#pragma unroll
            for (int na = 0; na < 8; na++) {
                int w = (na >> 1) * 128 + wbase + 2 * (na & 1);
                pfw[w]     = f2h2(s_[na][0], s_[na][1]);   // row g
                pfw[w + 1] = f2h2(s_[na][2], s_[na][3]);   // row g+8
            }
        }
        __syncwarp();

        // ---- O += P V (two d-atoms per ldsm4.trans) ----
#pragma unroll
        for (int ka = 0; ka < 4; ka++) {
            unsigned pa[4];
            *(uint4*)pa = *(const uint4*)&pfw[ka * 128 + lane * 4];
#pragma unroll
            for (int nap = 0; nap < 8; nap++) {
                unsigned b4[4];
                int na2  = 2 * nap + (grp >> 1);
                int vrow = ka * 16 + ((grp & 1) << 3) + (lane & 7);
                ldsm4t(b4, vbase + (vrow * KVPITCH + na2 * 8) * 2);
                mma16(o[2 * nap],     pa, b4);
                mma16(o[2 * nap + 1], pa, b4 + 2);
            }
        }

        scur++; if (scur >= APIPE) scur = 0;
    }

    // ---- epilogue: O / l, fp16 out ----
    float r0i = 1.f / l0, r1i = 1.f / l1;
    __half* Ob = oh + ((size_t)(b * NEWLEN + q0 + warp * 16)) * D_MODEL + h * DKDIM;
#pragma unroll
    for (int na = 0; na < 16; na++) {
        int c = na * 8 + tig * 2;
        *(unsigned*)(Ob + (size_t)gid * D_MODEL + c)       = f2h2(o[na][0] * r0i, o[na][1] * r0i);
        *(unsigned*)(Ob + (size_t)(gid + 8) * D_MODEL + c) = f2h2(o[na][2] * r1i, o[na][3] * r1i);
    }
}

// ---------------------------------------------------------------------------
// Launch
// ---------------------------------------------------------------------------
extern "C" void kernel_launch(void* const* d_in, const int* in_sizes, int n_in,
                              void* d_out, int out_size) {
    const float* x     = (const float*)d_in[0];
    const float* pastK = (const float*)d_in[1];
    const float* pastV = (const float*)d_in[2];
    const float* Wq    = (const float*)d_in[3];
    const float* Wk    = (const float*)d_in[4];
    const float* Wv    = (const float*)d_in[5];
    const float* Wo    = (const float*)d_in[6];
    float* out = (float*)d_out;

    __half *xh, *pkh, *pvh, *wqh, *wkh, *wvh, *woh, *qh, *kh, *vh, *oh;
    cudaGetSymbolAddress((void**)&xh,  g_xh);
    cudaGetSymbolAddress((void**)&pkh, g_pkh);
    cudaGetSymbolAddress((void**)&pvh, g_pvh);
    cudaGetSymbolAddress((void**)&wqh, g_wqh);
    cudaGetSymbolAddress((void**)&wkh, g_wkh);
    cudaGetSymbolAddress((void**)&wvh, g_wvh);
    cudaGetSymbolAddress((void**)&woh, g_woh);
    cudaGetSymbolAddress((void**)&qh,  g_qh);
    cudaGetSymbolAddress((void**)&kh,  g_kh);
    cudaGetSymbolAddress((void**)&vh,  g_vh);
    cudaGetSymbolAddress((void**)&oh,  g_oh);

    cudaFuncSetAttribute(gemm_qkv, cudaFuncAttributeMaxDynamicSharedMemorySize, GEMM_SMEM_BYTES);
    cudaFuncSetAttribute(gemm_out, cudaFuncAttributeMaxDynamicSharedMemorySize, GEMM_SMEM_BYTES);
    cudaFuncSetAttribute(attn_f16, cudaFuncAttributeMaxDynamicSharedMemorySize, ATTN_SMEM_BYTES);

    // ---- fp32 -> fp16 conversions (softmax scale folded into Wq) ----
    const float QSCL = 0.08838834764831845f * 1.4426950408889634f;  // 1/sqrt(dk)*log2e
    const int ACT4 = (int)(ACT_ELEMS / 4), W4 = (int)(W_ELEMS / 4);
    cvt16<<<ACT4 / 256, 256>>>((const float4*)x,     (__half2*)xh,  ACT4, 1.f);
    cvt16<<<ACT4 / 256, 256>>>((const float4*)pastK, (__half2*)pkh, ACT4, 1.f);
    cvt16<<<ACT4 / 256, 256>>>((const float4*)pastV, (__half2*)pvh, ACT4, 1.f);
    cvt16<<<W4 / 256, 256>>>((const float4*)Wq, (__half2*)wqh, W4, QSCL);
    cvt16<<<W4 / 256, 256>>>((const float4*)Wk, (__half2*)wkh, W4, 1.f);
    cvt16<<<W4 / 256, 256>>>((const float4*)Wv, (__half2*)wvh, W4, 1.f);
    cvt16<<<W4 / 256, 256>>>((const float4*)Wo, (__half2*)woh, W4, 1.f);

    dim3 qkv_grid(D_MODEL / 128, MROWS / 128, 3);   // (16, 32, 3)
    gemm_qkv<<<qkv_grid, 256, GEMM_SMEM_BYTES>>>(xh, wqh, wkh, wvh, qh, kh, vh);

    attn_f16<<<dim3(NEWLEN / QT, NH, BATCH), 256, ATTN_SMEM_BYTES>>>(qh, kh, vh, pkh, pvh, oh);

    dim3 gemm_grid(D_MODEL / 128, MROWS / 128);     // (16, 32)
    gemm_out<<<gemm_grid, 256, GEMM_SMEM_BYTES>>>(oh, woh, out);
}

// round 10
// speedup vs baseline: 9.0278x; 1.0689x over previous
#include <cuda_runtime.h>
#include <cuda_fp16.h>
#include <math.h>
#include <stdint.h>

#define D_MODEL 2048
#define NH      16
#define DKDIM   128
#define BATCH   2
#define NEWLEN  2048
#define PASTLEN 2048
#define MROWS   (BATCH * NEWLEN)   // 4096
#define ACT_ELEMS ((size_t)MROWS * D_MODEL)              // 8M
#define KV_ELEMS  ((size_t)BATCH * NH * PASTLEN * DKDIM) // 8M
#define W_ELEMS   ((size_t)D_MODEL * D_MODEL)            // 4M

// ---------------------------------------------------------------------------
// Scratch (device globals: allocation-free, harness-legal). All fp16.
// ---------------------------------------------------------------------------
__device__ __half g_xh[ACT_ELEMS];
__device__ __half g_pkh[KV_ELEMS];
__device__ __half g_pvh[KV_ELEMS];
__device__ __half g_wqh[W_ELEMS];
__device__ __half g_wkh[W_ELEMS];
__device__ __half g_wvh[W_ELEMS];
__device__ __half g_woh[W_ELEMS];
__device__ __half g_qh[ACT_ELEMS];
__device__ __half g_kh[ACT_ELEMS];
__device__ __half g_vh[ACT_ELEMS];
__device__ __half g_oh[ACT_ELEMS];

// ---------------------------------------------------------------------------
// Helpers
// ---------------------------------------------------------------------------
__device__ __forceinline__ unsigned f2h2(float lo, float hi) {
    unsigned u;
    asm("cvt.rn.f16x2.f32 %0, %1, %2;" : "=r"(u) : "f"(hi), "f"(lo));
    return u;
}

__device__ __forceinline__ float fexp2(float x) {
    float y;
    asm("ex2.approx.ftz.f32 %0, %1;" : "=f"(y) : "f"(x));
    return y;
}

__device__ __forceinline__ uint32_t smem_u32(const void* p) {
    uint32_t a;
    asm("{ .reg .u64 t; cvta.to.shared.u64 t, %1; cvt.u32.u64 %0, t; }" : "=r"(a) : "l"(p));
    return a;
}

__device__ __forceinline__ void mma16(float* d, const unsigned* a, const unsigned* b) {
    asm volatile(
        "mma.sync.aligned.m16n8k16.row.col.f32.f16.f16.f32 "
        "{%0,%1,%2,%3}, {%4,%5,%6,%7}, {%8,%9}, {%0,%1,%2,%3};\n"
        : "+f"(d[0]), "+f"(d[1]), "+f"(d[2]), "+f"(d[3])
        : "r"(a[0]), "r"(a[1]), "r"(a[2]), "r"(a[3]), "r"(b[0]), "r"(b[1]));
}

__device__ __forceinline__ void ldsm4(unsigned* r, uint32_t a) {
    asm volatile("ldmatrix.sync.aligned.m8n8.x4.shared.b16 {%0,%1,%2,%3}, [%4];"
                 : "=r"(r[0]), "=r"(r[1]), "=r"(r[2]), "=r"(r[3]) : "r"(a));
}
__device__ __forceinline__ void ldsm4t(unsigned* r, uint32_t a) {
    asm volatile("ldmatrix.sync.aligned.m8n8.x4.trans.shared.b16 {%0,%1,%2,%3}, [%4];"
                 : "=r"(r[0]), "=r"(r[1]), "=r"(r[2]), "=r"(r[3]) : "r"(a));
}

__device__ __forceinline__ void cp16(uint32_t dst, const void* src) {
    asm volatile("cp.async.cg.shared.global [%0], [%1], 16;"
                 :: "r"(dst), "l"((size_t)__cvta_generic_to_global(src)));
}
#define CP_COMMIT() asm volatile("cp.async.commit_group;" ::: "memory")
#define CP_WAIT(n)  asm volatile("cp.async.wait_group %0;" :: "n"(n) : "memory")

// ---------------------------------------------------------------------------
// Fused fp32 -> fp16 conversion for all 7 inputs (one launch)
// Segments (in float4 units): x 2M | pastK 2M | pastV 2M | Wq 1M | Wk 1M | Wv 1M | Wo 1M
// ---------------------------------------------------------------------------
#define ACT4 ((int)(ACT_ELEMS / 4))   // 2097152
#define W4   ((int)(W_ELEMS / 4))     // 1048576
#define TOT4 (3 * ACT4 + 4 * W4)      // 10485760

__global__ void cvt_all(const float4* __restrict__ x, const float4* __restrict__ pk,
                        const float4* __restrict__ pv, const float4* __restrict__ wq,
                        const float4* __restrict__ wk, const float4* __restrict__ wv,
                        const float4* __restrict__ wo,
                        __half2* __restrict__ xh, __half2* __restrict__ pkh,
                        __half2* __restrict__ pvh, __half2* __restrict__ wqh,
                        __half2* __restrict__ wkh, __half2* __restrict__ wvh,
                        __half2* __restrict__ woh, float qscale) {
    int i = blockIdx.x * blockDim.x + threadIdx.x;
    if (i >= TOT4) return;
    const float4* s;
    __half2* d;
    float scl = 1.f;
    int j = i;
    if (j < 3 * ACT4) {
        int seg = j / ACT4;  j -= seg * ACT4;
        s = (seg == 0) ? x : (seg == 1) ? pk : pv;
        d = (seg == 0) ? xh : (seg == 1) ? pkh : pvh;
    } else {
        j -= 3 * ACT4;
        int seg = j / W4;    j -= seg * W4;
        s = (seg == 0) ? wq : (seg == 1) ? wk : (seg == 2) ? wv : wo;
        d = (seg == 0) ? wqh : (seg == 1) ? wkh : (seg == 2) ? wvh : woh;
        if (seg == 0) scl = qscale;
    }
    float4 v = s[j];
    d[2 * j]     = __floats2half2_rn(v.x * scl, v.y * scl);
    d[2 * j + 1] = __floats2half2_rn(v.z * scl, v.w * scl);
}

// ---------------------------------------------------------------------------
// FP16 GEMM (NT): C[m][n] = sum_k A[m][k]*B[n][k];  A,B fp16, C fp16 or fp32.
// Block 128x128x32, 256 threads, warps 2(m) x 4(n), warp tile 64x32.
// 4-stage cp.async pipeline, ldmatrix.x4 fragment loads, 1 sync/iter.
// ---------------------------------------------------------------------------
#define BK 32
#define APITCH 40                                 // halves per row (pad 8)
#define GTILE_BYTES (128 * APITCH * 2)            // 10240
#define GSTAGE_BYTES (2 * GTILE_BYTES)            // 20480 (A then B)
#define GPIPE 4
#define GEMM_SMEM_BYTES (GPIPE * GSTAGE_BYTES)    // 81920

template <bool HALF_OUT>
__device__ __forceinline__ void gemm_body(const __half* __restrict__ A,
                                          const __half* __restrict__ B,
                                          void* __restrict__ Cv,
                                          char* smem, int m0, int n0) {
    const uint32_t sb = smem_u32(smem);
    const int K = D_MODEL, N = D_MODEL;
    const int tid  = threadIdx.x;
    const int lane = tid & 31;
    const int warp = tid >> 5;
    const int wm   = warp >> 2;
    const int wn   = warp & 3;
    const int gid  = lane >> 2;
    const int tig  = lane & 3;
    const int grp  = lane >> 3;          // 0..3 (ldmatrix 8-lane groups)

    auto issue = [&](int kt, int s) {
        uint32_t base = sb + s * GSTAGE_BYTES;
#pragma unroll
        for (int i = 0; i < 2; i++) {
            int c = tid + i * 256;               // 0..511
            int row  = c >> 2;                   // 0..127
            int colh = (c & 3) << 3;             // 0,8,16,24
            uint32_t d = base + (row * APITCH + colh) * 2;
            cp16(d, A + (size_t)(m0 + row) * K + kt * BK + colh);
            cp16(d + GTILE_BYTES, B + (size_t)(n0 + row) * K + kt * BK + colh);
        }
        CP_COMMIT();
    };

    float acc[4][4][4];
#pragma unroll
    for (int i = 0; i < 4; i++)
#pragma unroll
        for (int j = 0; j < 4; j++)
#pragma unroll
            for (int r = 0; r < 4; r++) acc[i][j][r] = 0.f;

    issue(0, 0); issue(1, 1); issue(2, 2);

    const int NKT = K / BK;   // 64
    for (int kt = 0; kt < NKT; kt++) {
        if (kt < NKT - 2)      CP_WAIT(2);
        else if (kt < NKT - 1) CP_WAIT(1);
        else                   CP_WAIT(0);
        __syncthreads();
        if (kt + 3 < NKT) issue(kt + 3, (kt + 3) & 3);

        uint32_t abase = sb + (kt & 3) * GSTAGE_BYTES;
        uint32_t bbase = abase + GTILE_BYTES;
#pragma unroll
        for (int ka = 0; ka < 2; ka++) {
            unsigned af[4][4], bf[4][2];
#pragma unroll
            for (int i = 0; i < 4; i++) {
                int row  = wm * 64 + i * 16 + (lane & 15);
                int colh = ka * 16 + ((lane >> 4) << 3);
                ldsm4(af[i], abase + (row * APITCH + colh) * 2);
            }
#pragma unroll
            for (int jp = 0; jp < 2; jp++) {
                unsigned b4[4];
                int j2   = 2 * jp + (grp >> 1);
                int nrow = wn * 32 + j2 * 8 + (lane & 7);
                int colh = ka * 16 + ((grp & 1) << 3);
                ldsm4(b4, bbase + (nrow * APITCH + colh) * 2);
                bf[2 * jp][0] = b4[0];     bf[2 * jp][1] = b4[1];
                bf[2 * jp + 1][0] = b4[2]; bf[2 * jp + 1][1] = b4[3];
            }
#pragma unroll
            for (int i = 0; i < 4; i++)
#pragma unroll
                for (int j = 0; j < 4; j++) mma16(acc[i][j], af[i], bf[j]);
        }
    }

#pragma unroll
    for (int i = 0; i < 4; i++) {
        int r0 = m0 + wm * 64 + i * 16 + gid;
#pragma unroll
        for (int j = 0; j < 4; j++) {
            int cc = n0 + wn * 32 + j * 8 + tig * 2;
            if (HALF_OUT) {
                __half* C = (__half*)Cv;
                *(unsigned*)(C + (size_t)r0 * N + cc)       = f2h2(acc[i][j][0], acc[i][j][1]);
                *(unsigned*)(C + (size_t)(r0 + 8) * N + cc) = f2h2(acc[i][j][2], acc[i][j][3]);
            } else {
                float* C = (float*)Cv;
                *(float2*)&C[(size_t)r0 * N + cc]       = make_float2(acc[i][j][0], acc[i][j][1]);
                *(float2*)&C[(size_t)(r0 + 8) * N + cc] = make_float2(acc[i][j][2], acc[i][j][3]);
            }
        }
    }
}

__global__ __launch_bounds__(256, 2) void gemm_qkv(const __half* __restrict__ x,
                                                   const __half* __restrict__ Wq,
                                                   const __half* __restrict__ Wk,
                                                   const __half* __restrict__ Wv,
                                                   __half* __restrict__ q,
                                                   __half* __restrict__ k,
                                                   __half* __restrict__ v) {
    extern __shared__ char sg[];
    const __half* B = (blockIdx.z == 0) ? Wq : (blockIdx.z == 1) ? Wk : Wv;
    __half* C = (blockIdx.z == 0) ? q : (blockIdx.z == 1) ? k : v;
    gemm_body<true>(x, B, C, sg, blockIdx.y * 128, blockIdx.x * 128);
}

__global__ __launch_bounds__(256, 2) void gemm_out(const __half* __restrict__ A,
                                                   const __half* __restrict__ B,
                                                   float* __restrict__ C) {
    extern __shared__ char sg[];
    gemm_body<false>(A, B, C, sg, blockIdx.y * 128, blockIdx.x * 128);
}

// ---------------------------------------------------------------------------
// Flash attention, fp16 m16n8k16, cp.async 3-stage K/V pipeline + ldmatrix.x4.
// Register-level P reuse (C-frag == A-frag layout for m16n8k16): no P restage.
// Grid (NEWLEN/128, NH, BATCH), 256 threads (8 warps), warp owns 16 q rows.
// ---------------------------------------------------------------------------
#define QT 128
#define KT 64
#define KVPITCH 136                               // halves per row (pad 8)
#define KVTILE_BYTES (KT * KVPITCH * 2)           // 17408
#define ASTAGE_BYTES (2 * KVTILE_BYTES)           // 34816 (K then V)
#define APIPE 3
#define ATTN_SMEM_BYTES (APIPE * ASTAGE_BYTES)    // 104448

__global__ __launch_bounds__(256, 1) void attn_f16(
    const __half* __restrict__ qh, const __half* __restrict__ kh,
    const __half* __restrict__ vh, const __half* __restrict__ pkh,
    const __half* __restrict__ pvh, __half* __restrict__ oh) {
    extern __shared__ char smem[];
    const uint32_t sb = smem_u32(smem);

    const int tid  = threadIdx.x;
    const int lane = tid & 31;
    const int warp = tid >> 5;
    const int gid  = lane >> 2;
    const int tig  = lane & 3;
    const int grp  = lane >> 3;          // 0..3
    const int q0 = (gridDim.x - 1 - blockIdx.x) * QT;   // largest-first
    const int h  = blockIdx.y;
    const int b  = blockIdx.z;

    const __half* Kn  = kh + (size_t)b * NEWLEN * D_MODEL + h * DKDIM;
    const __half* Vn  = vh + (size_t)b * NEWLEN * D_MODEL + h * DKDIM;
    const __half* pKb = pkh + (size_t)(b * NH + h) * PASTLEN * DKDIM;
    const __half* pVb = pvh + (size_t)(b * NH + h) * PASTLEN * DKDIM;

    // ---- Q fragments straight from fp16 global (already scaled via Wq) ----
    const __half* Qb = qh + ((size_t)(b * NEWLEN + q0 + warp * 16)) * D_MODEL + h * DKDIM;
    unsigned qf[8][4];
#pragma unroll
    for (int ka = 0; ka < 8; ka++) {
        int c0 = ka * 16 + 2 * tig;
        qf[ka][0] = *(const unsigned*)(Qb + (size_t)gid * D_MODEL + c0);
        qf[ka][1] = *(const unsigned*)(Qb + (size_t)(gid + 8) * D_MODEL + c0);
        qf[ka][2] = *(const unsigned*)(Qb + (size_t)gid * D_MODEL + c0 + 8);
        qf[ka][3] = *(const unsigned*)(Qb + (size_t)(gid + 8) * D_MODEL + c0 + 8);
    }

    float o[16][4];
#pragma unroll
    for (int na = 0; na < 16; na++)
#pragma unroll
        for (int r = 0; r < 4; r++) o[na][r] = 0.f;
    float m0 = -1e30f, m1 = -1e30f, l0 = 0.f, l1 = 0.f;

    auto issue = [&](int kt, int s) {
        uint32_t base = sb + s * ASTAGE_BYTES;
        int kb = kt * KT;
#pragma unroll
        for (int i = 0; i < 4; i++) {
            int c = tid + i * 256;               // 0..1023
            int row  = c >> 4;                   // 0..63
            int colh = (c & 15) << 3;            // 0..120
            int kg = kb + row;
            const __half *ks, *vs;
            if (kg < PASTLEN) {
                ks = pKb + (size_t)kg * DKDIM + colh;
                vs = pVb + (size_t)kg * DKDIM + colh;
            } else {
                size_t off = (size_t)(kg - PASTLEN) * D_MODEL + colh;
                ks = Kn + off;
                vs = Vn + off;
            }
            uint32_t d = base + (row * KVPITCH + colh) * 2;
            cp16(d, ks);
            cp16(d + KVTILE_BYTES, vs);
        }
        CP_COMMIT();
    };

    const int nkt = (PASTLEN + q0 + QT) / KT;
    const int qa0 = PASTLEN + q0 + warp * 16 + gid;

    issue(0, 0);
    if (nkt > 1) issue(1, 1);

    int scur = 0;
    for (int kt = 0; kt < nkt; kt++) {
        if (kt < nkt - 1) CP_WAIT(1);
        else              CP_WAIT(0);
        __syncthreads();
        if (kt + 2 < nkt) {
            int s2 = scur + 2; if (s2 >= APIPE) s2 -= APIPE;
            issue(kt + 2, s2);
        }
        const int kb = kt * KT;
        uint32_t kbase = sb + scur * ASTAGE_BYTES;
        uint32_t vbase = kbase + KVTILE_BYTES;

        // ---- S = Q K^T (two n-atoms per ldsm4) ----
        float s_[8][4];
#pragma unroll
        for (int na = 0; na < 8; na++)
#pragma unroll
            for (int r = 0; r < 4; r++) s_[na][r] = 0.f;
#pragma unroll
        for (int ka = 0; ka < 8; ka++) {
#pragma unroll
            for (int nap = 0; nap < 4; nap++) {
                unsigned b4[4];
                int na2  = 2 * nap + (grp >> 1);
                int krow = na2 * 8 + (lane & 7);
                int colh = ka * 16 + ((grp & 1) << 3);
                ldsm4(b4, kbase + (krow * KVPITCH + colh) * 2);
                mma16(s_[2 * nap],     qf[ka], b4);
                mma16(s_[2 * nap + 1], qf[ka], b4 + 2);
            }
        }

        // ---- causal mask ----
        if (kb + KT - 1 > qa0) {
#pragma unroll
            for (int na = 0; na < 8; na++) {
                int key = kb + na * 8 + tig * 2;
                if (key     > qa0)     s_[na][0] = -1e30f;
                if (key + 1 > qa0)     s_[na][1] = -1e30f;
                if (key     > qa0 + 8) s_[na][2] = -1e30f;
                if (key + 1 > qa0 + 8) s_[na][3] = -1e30f;
            }
        }

        // ---- online softmax (log2 domain), 4-lane row groups ----
        float mx0 = -1e30f, mx1 = -1e30f;
#pragma unroll
        for (int na = 0; na < 8; na++) {
            mx0 = fmaxf(mx0, fmaxf(s_[na][0], s_[na][1]));
            mx1 = fmaxf(mx1, fmaxf(s_[na][2], s_[na][3]));
        }
        mx0 = fmaxf(mx0, __shfl_xor_sync(0xffffffffu, mx0, 1));
        mx0 = fmaxf(mx0, __shfl_xor_sync(0xffffffffu, mx0, 2));
        mx1 = fmaxf(mx1, __shfl_xor_sync(0xffffffffu, mx1, 1));
        mx1 = fmaxf(mx1, __shfl_xor_sync(0xffffffffu, mx1, 2));
        float nm0 = fmaxf(m0, mx0), nm1 = fmaxf(m1, mx1);
        float c0 = fexp2(m0 - nm0), c1 = fexp2(m1 - nm1);
        float sum0 = 0.f, sum1 = 0.f;
#pragma unroll
        for (int na = 0; na < 8; na++) {
            s_[na][0] = fexp2(s_[na][0] - nm0); sum0 += s_[na][0];
            s_[na][1] = fexp2(s_[na][1] - nm0); sum0 += s_[na][1];
            s_[na][2] = fexp2(s_[na][2] - nm1); sum1 += s_[na][2];
            s_[na][3] = fexp2(s_[na][3] - nm1); sum1 += s_[na][3];
        }
        sum0 += __shfl_xor_sync(0xffffffffu, sum0, 1);
        sum0 += __shfl_xor_sync(0xffffffffu, sum0, 2);
        sum1 += __shfl_xor_sync(0xffffffffu, sum1, 1);
        sum1 += __shfl_xor_sync(0xffffffffu, sum1, 2);
        l0 = l0 * c0 + sum0;
        l1 = l1 * c1 + sum1;
        m0 = nm0; m1 = nm1;

        // ---- rescale O ----
#pragma unroll
        for (int na = 0; na < 16; na++) {
            o[na][0] *= c0; o[na][1] *= c0;
            o[na][2] *= c1; o[na][3] *= c1;
        }

        // ---- P in registers: C-frag == A-frag layout for m16n8k16 ----
        // keys 16ka..16ka+15 = S atoms {2ka, 2ka+1}:
        //  a0={P[g][2t],P[g][2t+1]}   = s_[2ka][0..1]
        //  a1={P[g+8][2t],...}        = s_[2ka][2..3]
        //  a2={P[g][8+2t],...}        = s_[2ka+1][0..1]
        //  a3={P[g+8][8+2t],...}      = s_[2ka+1][2..3]
#pragma unroll
        for (int ka = 0; ka < 4; ka++) {
            unsigned pa[4];
            pa[0] = f2h2(s_[2 * ka][0],     s_[2 * ka][1]);
            pa[1] = f2h2(s_[2 * ka][2],     s_[2 * ka][3]);
            pa[2] = f2h2(s_[2 * ka + 1][0], s_[2 * ka + 1][1]);
            pa[3] = f2h2(s_[2 * ka + 1][2], s_[2 * ka + 1][3]);
#pragma unroll
            for (int nap = 0; nap < 8; nap++) {
                unsigned b4[4];
                int na2  = 2 * nap + (grp >> 1);
                int vrow = ka * 16 + ((grp & 1) << 3) + (lane & 7);
                ldsm4t(b4, vbase + (vrow * KVPITCH + na2 * 8) * 2);
                mma16(o[2 * nap],     pa, b4);
                mma16(o[2 * nap + 1], pa, b4 + 2);
            }
        }

        scur++; if (scur >= APIPE) scur = 0;
    }

    // ---- epilogue: O / l, fp16 out ----
    float r0i = 1.f / l0, r1i = 1.f / l1;
    __half* Ob = oh + ((size_t)(b * NEWLEN + q0 + warp * 16)) * D_MODEL + h * DKDIM;
#pragma unroll
    for (int na = 0; na < 16; na++) {
        int c = na * 8 + tig * 2;
        *(unsigned*)(Ob + (size_t)gid * D_MODEL + c)       = f2h2(o[na][0] * r0i, o[na][1] * r0i);
        *(unsigned*)(Ob + (size_t)(gid + 8) * D_MODEL + c) = f2h2(o[na][2] * r1i, o[na][3] * r1i);
    }
}

// ---------------------------------------------------------------------------
// Launch
// ---------------------------------------------------------------------------
extern "C" void kernel_launch(void* const* d_in, const int* in_sizes, int n_in,
                              void* d_out, int out_size) {
    const float* x     = (const float*)d_in[0];
    const float* pastK = (const float*)d_in[1];
    const float* pastV = (const float*)d_in[2];
    const float* Wq    = (const float*)d_in[3];
    const float* Wk    = (const float*)d_in[4];
    const float* Wv    = (const float*)d_in[5];
    const float* Wo    = (const float*)d_in[6];
    float* out = (float*)d_out;

    __half *xh, *pkh, *pvh, *wqh, *wkh, *wvh, *woh, *qh, *kh, *vh, *oh;
    cudaGetSymbolAddress((void**)&xh,  g_xh);
    cudaGetSymbolAddress((void**)&pkh, g_pkh);
    cudaGetSymbolAddress((void**)&pvh, g_pvh);
    cudaGetSymbolAddress((void**)&wqh, g_wqh);
    cudaGetSymbolAddress((void**)&wkh, g_wkh);
    cudaGetSymbolAddress((void**)&wvh, g_wvh);
    cudaGetSymbolAddress((void**)&woh, g_woh);
    cudaGetSymbolAddress((void**)&qh,  g_qh);
    cudaGetSymbolAddress((void**)&kh,  g_kh);
    cudaGetSymbolAddress((void**)&vh,  g_vh);
    cudaGetSymbolAddress((void**)&oh,  g_oh);

    cudaFuncSetAttribute(gemm_qkv, cudaFuncAttributeMaxDynamicSharedMemorySize, GEMM_SMEM_BYTES);
    cudaFuncSetAttribute(gemm_out, cudaFuncAttributeMaxDynamicSharedMemorySize, GEMM_SMEM_BYTES);
    cudaFuncSetAttribute(attn_f16, cudaFuncAttributeMaxDynamicSharedMemorySize, ATTN_SMEM_BYTES);

    // ---- fused fp32 -> fp16 conversion (softmax scale folded into Wq) ----
    const float QSCL = 0.08838834764831845f * 1.4426950408889634f;  // 1/sqrt(dk)*log2e
    cvt_all<<<(TOT4 + 255) / 256, 256>>>(
        (const float4*)x, (const float4*)pastK, (const float4*)pastV,
        (const float4*)Wq, (const float4*)Wk, (const float4*)Wv, (const float4*)Wo,
        (__half2*)xh, (__half2*)pkh, (__half2*)pvh,
        (__half2*)wqh, (__half2*)wkh, (__half2*)wvh, (__half2*)woh, QSCL);

    dim3 qkv_grid(D_MODEL / 128, MROWS / 128, 3);   // (16, 32, 3)
    gemm_qkv<<<qkv_grid, 256, GEMM_SMEM_BYTES>>>(xh, wqh, wkh, wvh, qh, kh, vh);

    attn_f16<<<dim3(NEWLEN / QT, NH, BATCH), 256, ATTN_SMEM_BYTES>>>(qh, kh, vh, pkh, pvh, oh);

    dim3 gemm_grid(D_MODEL / 128, MROWS / 128);     // (16, 32)
    gemm_out<<<gemm_grid, 256, GEMM_SMEM_BYTES>>>(oh, woh, out);
}